// round 2
// baseline (speedup 1.0000x reference)
#include <cuda_runtime.h>
#include <math.h>

#define Bb   64
#define Tt   256
#define INd  512
#define Hd   1024
#define OUTd 512
#define G4   (4*Hd)        // 4096
#define Mrows (Bb*Tt)      // 16384

// Scratch (device globals; no allocation allowed)
__device__ float g_xp[(size_t)Mrows * G4];   // [B*T, 4H]  input projection + bias
__device__ float g_hs[(size_t)Mrows * Hd];   // [B*T, H]   all hidden states
__device__ float g_hbuf[2][Bb * Hd];         // h ping-pong
__device__ float g_c[Bb * Hd];               // cell state

// ---------------------------------------------------------------------------
__global__ void zero_state() {
    int i = blockIdx.x * blockDim.x + threadIdx.x;
    if (i < Bb * Hd) { g_hbuf[0][i] = 0.f; g_c[i] = 0.f; }
}

// ---------------------------------------------------------------------------
// C[M,N] = A[M,K] @ W[K,N] + bias[N]. Tiles: 64x64, BK=64, 256 threads, 4x4/thread.
template<int K>
__global__ __launch_bounds__(256)
void gemm_bias(const float* __restrict__ A, const float* __restrict__ W,
               const float* __restrict__ bias, float* __restrict__ C, int N) {
    __shared__ float As[64][68];   // As[kk][row]
    __shared__ float Ws[64][68];   // Ws[kk][col]

    const int tid = threadIdx.x;
    const int tx = tid & 15;       // col group
    const int ty = tid >> 4;       // row group
    const int rowBase = blockIdx.y * 64;
    const int colBase = blockIdx.x * 64;

    float acc[4][4] = {};

    for (int k0 = 0; k0 < K; k0 += 64) {
        // A tile, stored transposed As[kk][row]
        #pragma unroll
        for (int r = 0; r < 4; r++) {
            int fi  = r * 256 + tid;          // 0..1023
            int row = fi >> 4;
            int q   = fi & 15;
            float4 v = *(const float4*)&A[(size_t)(rowBase + row) * K + k0 + q * 4];
            As[q*4+0][row] = v.x;
            As[q*4+1][row] = v.y;
            As[q*4+2][row] = v.z;
            As[q*4+3][row] = v.w;
        }
        // W tile Ws[kk][col]
        #pragma unroll
        for (int r = 0; r < 4; r++) {
            int fi = r * 256 + tid;
            int kk = fi >> 4;
            int q  = fi & 15;
            float4 v = *(const float4*)&W[(size_t)(k0 + kk) * N + colBase + q * 4];
            *(float4*)&Ws[kk][q * 4] = v;
        }
        __syncthreads();

        #pragma unroll 16
        for (int kk = 0; kk < 64; kk++) {
            float4 a = *(const float4*)&As[kk][ty * 4];
            float4 w = *(const float4*)&Ws[kk][tx * 4];
            float av[4] = {a.x, a.y, a.z, a.w};
            float wv[4] = {w.x, w.y, w.z, w.w};
            #pragma unroll
            for (int i = 0; i < 4; i++)
                #pragma unroll
                for (int j = 0; j < 4; j++)
                    acc[i][j] += av[i] * wv[j];
        }
        __syncthreads();
    }

    #pragma unroll
    for (int i = 0; i < 4; i++) {
        int row = rowBase + ty * 4 + i;
        #pragma unroll
        for (int j = 0; j < 4; j++) {
            int col = colBase + tx * 4 + j;
            C[(size_t)row * N + col] = acc[i][j] + bias[col];
        }
    }
}

// ---------------------------------------------------------------------------
// One LSTM timestep, fused: gates = xp[:,t,:] + h@Wh (+b already in xp),
// nonlinearity, c/h update. grid=128 blocks (j-tile of 8 hidden cols),
// block=128 threads. Thread (ty,tx): 4 batch rows {ty,ty+16,ty+32,ty+48},
// 1 col j0+tx, all 4 gates -> 16 accumulators.
__global__ __launch_bounds__(128)
void lstm_step(const float* __restrict__ Wh, const float* __restrict__ h_in,
               float* __restrict__ h_out, int t) {
    __shared__ float hS[64][68];        // hS[b][kk]
    __shared__ float wS[4 * 64 * 8];    // [g][kk][tx]

    const int tid = threadIdx.x;        // 0..127
    const int tx = tid & 7;
    const int ty = tid >> 3;            // 0..15
    const int j0 = blockIdx.x * 8;

    float acc[4][4] = {};               // [gate][batch-quarter]

    for (int k0 = 0; k0 < Hd; k0 += 64) {
        // h tile: 4096 floats
        #pragma unroll
        for (int r = 0; r < 8; r++) {
            int fi = r * 128 + tid;     // 0..1023
            int b  = fi >> 4;
            int q  = fi & 15;
            float4 v = *(const float4*)&h_in[b * Hd + k0 + q * 4];
            *(float4*)&hS[b][q * 4] = v;
        }
        // Wh tile: rows k0..k0+63, 4 gate column groups of 8
        #pragma unroll
        for (int r = 0; r < 4; r++) {
            int fi = r * 128 + tid;     // 0..511
            int j4 = fi & 1;
            int g  = (fi >> 1) & 3;
            int kk = fi >> 3;
            float4 v = *(const float4*)&Wh[(size_t)(k0 + kk) * G4 + g * Hd + j0 + j4 * 4];
            *(float4*)&wS[((g * 64) + kk) * 8 + j4 * 4] = v;
        }
        __syncthreads();

        #pragma unroll 16
        for (int kk = 0; kk < 64; kk++) {
            float h0 = hS[ty][kk];
            float h1 = hS[ty + 16][kk];
            float h2 = hS[ty + 32][kk];
            float h3 = hS[ty + 48][kk];
            #pragma unroll
            for (int g = 0; g < 4; g++) {
                float w = wS[(g * 64 + kk) * 8 + tx];
                acc[g][0] += h0 * w;
                acc[g][1] += h1 * w;
                acc[g][2] += h2 * w;
                acc[g][3] += h3 * w;
            }
        }
        __syncthreads();
    }

    const int j = j0 + tx;
    #pragma unroll
    for (int bi = 0; bi < 4; bi++) {
        int b = ty + bi * 16;
        const float* xpr = &g_xp[((size_t)b * Tt + t) * G4];
        float gi = acc[0][bi] + xpr[0 * Hd + j];
        float gf = acc[1][bi] + xpr[1 * Hd + j];
        float gg = acc[2][bi] + xpr[2 * Hd + j];
        float go = acc[3][bi] + xpr[3 * Hd + j];

        float si = 1.f / (1.f + expf(-gi));
        float sf = 1.f / (1.f + expf(-gf));
        float so = 1.f / (1.f + expf(-go));
        float tg = tanhf(gg);

        float cO = g_c[b * Hd + j];
        float cN = sf * cO + si * tg;
        g_c[b * Hd + j] = cN;
        float hN = so * tanhf(cN);
        h_out[b * Hd + j] = hN;
        g_hs[((size_t)b * Tt + t) * Hd + j] = hN;
    }
}

// ---------------------------------------------------------------------------
extern "C" void kernel_launch(void* const* d_in, const int* in_sizes, int n_in,
                              void* d_out, int out_size) {
    const float* xs = (const float*)d_in[0];
    const float* Wi = (const float*)d_in[1];
    const float* Wh = (const float*)d_in[2];
    const float* b  = (const float*)d_in[3];
    const float* Wo = (const float*)d_in[4];
    const float* bo = (const float*)d_in[5];
    float* out = (float*)d_out;

    float *xp_p = nullptr, *hs_p = nullptr, *hbuf_p = nullptr;
    cudaGetSymbolAddress((void**)&xp_p, g_xp);
    cudaGetSymbolAddress((void**)&hs_p, g_hs);
    cudaGetSymbolAddress((void**)&hbuf_p, g_hbuf);

    // 1) zero initial state
    zero_state<<<(Bb * Hd + 255) / 256, 256>>>();

    // 2) xp = xs @ Wi + b   (M=16384, K=512, N=4096)
    {
        dim3 grid(G4 / 64, Mrows / 64);
        gemm_bias<INd><<<grid, 256>>>(xs, Wi, b, xp_p, G4);
    }

    // 3) 256 recurrent steps, h ping-pong
    for (int t = 0; t < Tt; t++) {
        const float* h_in = hbuf_p + (size_t)(t & 1) * (Bb * Hd);
        float* h_out      = hbuf_p + (size_t)((t + 1) & 1) * (Bb * Hd);
        lstm_step<<<128, 128>>>(Wh, h_in, h_out, t);
    }

    // 4) logits = hs @ Wo + bo   (M=16384, K=1024, N=512)
    {
        dim3 grid(OUTd / 64, Mrows / 64);
        gemm_bias<Hd><<<grid, 256>>>(hs_p, Wo, bo, out, OUTd);
    }
}

// round 3
// speedup vs baseline: 1.2835x; 1.2835x over previous
#include <cuda_runtime.h>
#include <math.h>

#define Bb   64
#define Tt   256
#define INd  512
#define Hd   1024
#define OUTd 512
#define G4   (4*Hd)        // 4096
#define Mrows (Bb*Tt)      // 16384

// Scratch (device globals; no allocation allowed)
__device__ float g_xp[(size_t)Mrows * G4];   // [B*T, 4H]  input projection + bias
__device__ float g_hs[(size_t)Mrows * Hd];   // [B*T, H]   all hidden states
__device__ float g_hbuf[2][Bb * Hd];         // h ping-pong
__device__ float g_c[Bb * Hd];               // cell state

// ---------------------------------------------------------------------------
__global__ void zero_state() {
    int i = blockIdx.x * blockDim.x + threadIdx.x;
    if (i < Bb * Hd) { g_hbuf[0][i] = 0.f; g_c[i] = 0.f; }
}

// ---------------------------------------------------------------------------
// C[M,N] = A[M,K] @ W[K,N] + bias[N]. Tiles: 64x64, BK=64, 256 threads, 4x4/thread.
template<int K>
__global__ __launch_bounds__(256)
void gemm_bias(const float* __restrict__ A, const float* __restrict__ W,
               const float* __restrict__ bias, float* __restrict__ C, int N) {
    __shared__ float As[64][68];   // As[kk][row]
    __shared__ float Ws[64][68];   // Ws[kk][col]

    const int tid = threadIdx.x;
    const int tx = tid & 15;       // col group
    const int ty = tid >> 4;       // row group
    const int rowBase = blockIdx.y * 64;
    const int colBase = blockIdx.x * 64;

    float acc[4][4] = {};

    for (int k0 = 0; k0 < K; k0 += 64) {
        // A tile, stored transposed As[kk][row]
        #pragma unroll
        for (int r = 0; r < 4; r++) {
            int fi  = r * 256 + tid;          // 0..1023
            int row = fi >> 4;
            int q   = fi & 15;
            float4 v = *(const float4*)&A[(size_t)(rowBase + row) * K + k0 + q * 4];
            As[q*4+0][row] = v.x;
            As[q*4+1][row] = v.y;
            As[q*4+2][row] = v.z;
            As[q*4+3][row] = v.w;
        }
        // W tile Ws[kk][col]
        #pragma unroll
        for (int r = 0; r < 4; r++) {
            int fi = r * 256 + tid;
            int kk = fi >> 4;
            int q  = fi & 15;
            float4 v = *(const float4*)&W[(size_t)(k0 + kk) * N + colBase + q * 4];
            *(float4*)&Ws[kk][q * 4] = v;
        }
        __syncthreads();

        #pragma unroll 16
        for (int kk = 0; kk < 64; kk++) {
            float4 a = *(const float4*)&As[kk][ty * 4];
            float4 w = *(const float4*)&Ws[kk][tx * 4];
            float av[4] = {a.x, a.y, a.z, a.w};
            float wv[4] = {w.x, w.y, w.z, w.w};
            #pragma unroll
            for (int i = 0; i < 4; i++)
                #pragma unroll
                for (int j = 0; j < 4; j++)
                    acc[i][j] += av[i] * wv[j];
        }
        __syncthreads();
    }

    #pragma unroll
    for (int i = 0; i < 4; i++) {
        int row = rowBase + ty * 4 + i;
        #pragma unroll
        for (int j = 0; j < 4; j++) {
            int col = colBase + tx * 4 + j;
            C[(size_t)row * N + col] = acc[i][j] + bias[col];
        }
    }
}

// ---------------------------------------------------------------------------
// Fused LSTM step, split-K over 4 warpgroups.
// grid = 128 blocks (each owns 8 hidden columns j0..j0+7, all 4 gates -> N=32
// effective columns), block = 512 threads = 4 groups x 128.
// Group g accumulates over K in [g*256, (g+1)*256). Each thread: 4 batch rows
// x (4 gates of one hidden col) = 16 accumulators (4x4 register blocking).
// Groups 1..3 dump partials to smem; group 0 reduces + applies nonlinearity.
#define SK  4
#define KG  (Hd / SK)   // 256
#define BK  64
#define NJ  8
#define HPAD 68
#define SM_FLOATS (SK*BK*HPAD + SK*BK*32)   // 17408 + 8192 = 25600 floats

__global__ __launch_bounds__(512)
void lstm_step(const float* __restrict__ Wh, const float* __restrict__ h_in,
               float* __restrict__ h_out, int t) {
    extern __shared__ float sm[];
    float* hS = sm;                       // [SK][BK][HPAD]  (transposed: [kk][b])
    float* wS = sm + SK * BK * HPAD;      // [SK][BK][32]    ([kk][gate*8+jj])

    const int tid = threadIdx.x;
    const int grp = tid >> 7;             // 0..3
    const int lt  = tid & 127;            // 0..127 within group
    const int ty  = lt >> 3;              // 0..15 -> rows 4*ty..4*ty+3
    const int tx  = lt & 7;               // 0..7  -> hidden col j0+tx
    const int j0  = blockIdx.x * NJ;

    float acc[4][4] = {};                 // [gate][row]

    float* hSg = hS + grp * BK * HPAD;
    float* wSg = wS + grp * BK * 32;
    const int kgrp = grp * KG;

    #pragma unroll
    for (int kt = 0; kt < KG; kt += BK) {
        const int kb = kgrp + kt;
        // h tile (this group's K slice), stored transposed hSg[kk][b]
        #pragma unroll
        for (int r = 0; r < 8; r++) {
            int fi = r * 128 + lt;        // 0..1023
            int b  = fi >> 4;
            int q  = fi & 15;
            float4 v = *(const float4*)&h_in[b * Hd + kb + q * 4];
            hSg[(q*4+0) * HPAD + b] = v.x;
            hSg[(q*4+1) * HPAD + b] = v.y;
            hSg[(q*4+2) * HPAD + b] = v.z;
            hSg[(q*4+3) * HPAD + b] = v.w;
        }
        // Wh tile: rows kb..kb+63, 4 gate column groups of 8
        #pragma unroll
        for (int r = 0; r < 4; r++) {
            int fi = r * 128 + lt;        // 0..511
            int j4 = fi & 1;
            int g  = (fi >> 1) & 3;
            int kk = fi >> 3;
            float4 v = *(const float4*)&Wh[(size_t)(kb + kk) * G4 + g * Hd + j0 + j4 * 4];
            *(float4*)&wSg[kk * 32 + g * 8 + j4 * 4] = v;
        }
        __syncthreads();

        #pragma unroll
        for (int kk = 0; kk < BK; kk++) {
            float4 hv = *(const float4*)&hSg[kk * HPAD + ty * 4];
            float h0 = hv.x, h1 = hv.y, h2 = hv.z, h3 = hv.w;
            #pragma unroll
            for (int g = 0; g < 4; g++) {
                float w = wSg[kk * 32 + g * 8 + tx];
                acc[g][0] += h0 * w;
                acc[g][1] += h1 * w;
                acc[g][2] += h2 * w;
                acc[g][3] += h3 * w;
            }
        }
        __syncthreads();
    }

    // split-K reduction through smem (reuse hS region; all compute is done)
    float* red = sm;                      // [3][128][16]
    if (grp > 0) {
        float* dst = red + ((grp - 1) * 128 + lt) * 16;
        #pragma unroll
        for (int g = 0; g < 4; g++)
            #pragma unroll
            for (int i = 0; i < 4; i++)
                dst[g * 4 + i] = acc[g][i];
    }
    __syncthreads();

    if (grp == 0) {
        #pragma unroll
        for (int p = 0; p < 3; p++) {
            const float* src = red + (p * 128 + lt) * 16;
            #pragma unroll
            for (int g = 0; g < 4; g++)
                #pragma unroll
                for (int i = 0; i < 4; i++)
                    acc[g][i] += src[g * 4 + i];
        }
        const int j = j0 + tx;
        #pragma unroll
        for (int i = 0; i < 4; i++) {
            int b = ty * 4 + i;
            const float* xpr = &g_xp[((size_t)b * Tt + t) * G4];
            float gi = acc[0][i] + xpr[0 * Hd + j];
            float gf = acc[1][i] + xpr[1 * Hd + j];
            float gg = acc[2][i] + xpr[2 * Hd + j];
            float go = acc[3][i] + xpr[3 * Hd + j];

            float si = 1.f / (1.f + expf(-gi));
            float sf = 1.f / (1.f + expf(-gf));
            float so = 1.f / (1.f + expf(-go));
            float tg = tanhf(gg);

            float cO = g_c[b * Hd + j];
            float cN = sf * cO + si * tg;
            g_c[b * Hd + j] = cN;
            float hN = so * tanhf(cN);
            h_out[b * Hd + j] = hN;
            g_hs[((size_t)b * Tt + t) * Hd + j] = hN;
        }
    }
}

// ---------------------------------------------------------------------------
extern "C" void kernel_launch(void* const* d_in, const int* in_sizes, int n_in,
                              void* d_out, int out_size) {
    const float* xs = (const float*)d_in[0];
    const float* Wi = (const float*)d_in[1];
    const float* Wh = (const float*)d_in[2];
    const float* b  = (const float*)d_in[3];
    const float* Wo = (const float*)d_in[4];
    const float* bo = (const float*)d_in[5];
    float* out = (float*)d_out;

    float *xp_p = nullptr, *hs_p = nullptr, *hbuf_p = nullptr;
    cudaGetSymbolAddress((void**)&xp_p, g_xp);
    cudaGetSymbolAddress((void**)&hs_p, g_hs);
    cudaGetSymbolAddress((void**)&hbuf_p, g_hbuf);

    const int smem_bytes = SM_FLOATS * sizeof(float);   // 102400
    cudaFuncSetAttribute(lstm_step, cudaFuncAttributeMaxDynamicSharedMemorySize,
                         smem_bytes);

    // 1) zero initial state
    zero_state<<<(Bb * Hd + 255) / 256, 256>>>();

    // 2) xp = xs @ Wi + b   (M=16384, K=512, N=4096)
    {
        dim3 grid(G4 / 64, Mrows / 64);
        gemm_bias<INd><<<grid, 256>>>(xs, Wi, b, xp_p, G4);
    }

    // 3) 256 recurrent steps, h ping-pong
    for (int t = 0; t < Tt; t++) {
        const float* h_in = hbuf_p + (size_t)(t & 1) * (Bb * Hd);
        float* h_out      = hbuf_p + (size_t)((t + 1) & 1) * (Bb * Hd);
        lstm_step<<<128, 512, smem_bytes>>>(Wh, h_in, h_out, t);
    }

    // 4) logits = hs @ Wo + bo   (M=16384, K=1024, N=512)
    {
        dim3 grid(OUTd / 64, Mrows / 64);
        gemm_bias<Hd><<<grid, 256>>>(hs_p, Wo, bo, out, OUTd);
    }
}

// round 5
// speedup vs baseline: 1.6301x; 1.2700x over previous
#include <cuda_runtime.h>
#include <cuda_bf16.h>
#include <math.h>
#include <stdint.h>

#define Bb   64
#define Tt   256
#define INd  512
#define Hd   1024
#define OUTd 512
#define G4   (4*Hd)        // 4096
#define Mrows (Bb*Tt)      // 16384

#define NBLK 128           // step-kernel blocks; each owns 8 hidden cols (x4 gates = N=32)
#define NJJ  8             // hidden cols per block
#define NKS  64            // k16 steps (K=1024)

// ---------------- scratch (device globals) ----------------
__device__ float g_xp[(size_t)Mrows * G4];        // [B*T, 4H]
__device__ float g_hs[(size_t)Mrows * Hd];        // [B*T, H]
__device__ float g_c[Bb * Hd];                    // cell state
__device__ __nv_bfloat16 g_hh[2][Bb * Hd];        // h hi split (ping-pong)
__device__ __nv_bfloat16 g_hl[2][Bb * Hd];        // h lo split
// Wh pre-scattered into HMMA B-fragment order:
// [blk][ks][wx][lane] -> uint4 {b0_t0, b1_t0, b0_t1, b1_t1}
__device__ uint4 g_Bfh[(size_t)NBLK * NKS * 2 * 32];
__device__ uint4 g_Bfl[(size_t)NBLK * NKS * 2 * 32];

#define SW128(b) ((b) ^ (((b) >> 3) & 0x70))

__device__ __forceinline__ uint32_t smem_u32(const void* p) {
    uint32_t a;
    asm("{ .reg .u64 t; cvta.to.shared.u64 t, %1; cvt.u32.u64 %0, t; }" : "=r"(a) : "l"(p));
    return a;
}
__device__ __forceinline__ void ldmatrix_x4(uint32_t* r, uint32_t addr) {
    asm volatile("ldmatrix.sync.aligned.m8n8.x4.shared.b16 {%0,%1,%2,%3}, [%4];"
                 : "=r"(r[0]), "=r"(r[1]), "=r"(r[2]), "=r"(r[3]) : "r"(addr));
}
__device__ __forceinline__ void mma_bf16(float* c, const uint32_t* a,
                                         uint32_t b0, uint32_t b1) {
    asm volatile(
        "mma.sync.aligned.m16n8k16.row.col.f32.bf16.bf16.f32 "
        "{%0,%1,%2,%3}, {%4,%5,%6,%7}, {%8,%9}, {%0,%1,%2,%3};"
        : "+f"(c[0]), "+f"(c[1]), "+f"(c[2]), "+f"(c[3])
        : "r"(a[0]), "r"(a[1]), "r"(a[2]), "r"(a[3]), "r"(b0), "r"(b1));
}
__device__ __forceinline__ uint32_t pack_bf16(float x, float y) {
    __nv_bfloat162 v = __floats2bfloat162_rn(x, y);
    return *(uint32_t*)&v;
}

// ---------------------------------------------------------------------------
__global__ void zero_state() {
    int i = blockIdx.x * blockDim.x + threadIdx.x;
    if (i < Bb * Hd) {
        g_c[i] = 0.f;
        g_hh[0][i] = __float2bfloat16(0.f);
        g_hl[0][i] = __float2bfloat16(0.f);
    }
}

// ---------------------------------------------------------------------------
// Scatter Wh (fp32 [1024][4096]) into per-lane B-fragment order, bf16 hi/lo.
// One thread per (blk, ks, wx, lane): builds uint4 {b0_t0,b1_t0,b0_t1,b1_t1}.
// Fragment layout (m16n8k16 row.col): b0 = pack(B[k0+2c], B[k0+2c+1]),
// b1 = pack(B[k0+8+2c], B[k0+9+2c]); c = lane%4, n = lane/4.
__global__ __launch_bounds__(256) void prep_Bfrag(const float* __restrict__ Wh) {
    int gid = blockIdx.x * blockDim.x + threadIdx.x;    // 0 .. 524287
    int lane = gid & 31;
    int wx   = (gid >> 5) & 1;
    int ks   = (gid >> 6) & 63;
    int blk  = gid >> 12;

    uint32_t outh[4], outl[4];
    #pragma unroll
    for (int t2 = 0; t2 < 2; t2++) {
        int loc = wx * 16 + t2 * 8 + (lane >> 2);       // local gate-col 0..31
        int g = loc >> 3, jj = loc & 7;
        int col = g * Hd + blk * NJJ + jj;              // global col in 4H
        int kb = ks * 16 + (lane & 3) * 2;
        float w0 = Wh[(size_t)(kb + 0) * G4 + col];
        float w1 = Wh[(size_t)(kb + 1) * G4 + col];
        float w8 = Wh[(size_t)(kb + 8) * G4 + col];
        float w9 = Wh[(size_t)(kb + 9) * G4 + col];
        float h0 = __bfloat162float(__float2bfloat16_rn(w0));
        float h1 = __bfloat162float(__float2bfloat16_rn(w1));
        float h8 = __bfloat162float(__float2bfloat16_rn(w8));
        float h9 = __bfloat162float(__float2bfloat16_rn(w9));
        outh[t2*2+0] = pack_bf16(h0, h1);
        outh[t2*2+1] = pack_bf16(h8, h9);
        outl[t2*2+0] = pack_bf16(w0 - h0, w1 - h1);
        outl[t2*2+1] = pack_bf16(w8 - h8, w9 - h9);
    }
    g_Bfh[gid] = make_uint4(outh[0], outh[1], outh[2], outh[3]);
    g_Bfl[gid] = make_uint4(outl[0], outl[1], outl[2], outl[3]);
}

// ---------------------------------------------------------------------------
// C[M,N] = A[M,K] @ W[K,N] + bias[N]. fp32 SIMT GEMM (unchanged).
template<int K>
__global__ __launch_bounds__(256)
void gemm_bias(const float* __restrict__ A, const float* __restrict__ W,
               const float* __restrict__ bias, float* __restrict__ C, int N) {
    __shared__ float As[64][68];
    __shared__ float Ws[64][68];
    const int tid = threadIdx.x;
    const int tx = tid & 15, ty = tid >> 4;
    const int rowBase = blockIdx.y * 64, colBase = blockIdx.x * 64;
    float acc[4][4] = {};
    for (int k0 = 0; k0 < K; k0 += 64) {
        #pragma unroll
        for (int r = 0; r < 4; r++) {
            int fi = r * 256 + tid; int row = fi >> 4; int q = fi & 15;
            float4 v = *(const float4*)&A[(size_t)(rowBase + row) * K + k0 + q * 4];
            As[q*4+0][row] = v.x; As[q*4+1][row] = v.y;
            As[q*4+2][row] = v.z; As[q*4+3][row] = v.w;
        }
        #pragma unroll
        for (int r = 0; r < 4; r++) {
            int fi = r * 256 + tid; int kk = fi >> 4; int q = fi & 15;
            *(float4*)&Ws[kk][q * 4] =
                *(const float4*)&W[(size_t)(k0 + kk) * N + colBase + q * 4];
        }
        __syncthreads();
        #pragma unroll 16
        for (int kk = 0; kk < 64; kk++) {
            float4 a = *(const float4*)&As[kk][ty * 4];
            float4 w = *(const float4*)&Ws[kk][tx * 4];
            float av[4] = {a.x,a.y,a.z,a.w}, wv[4] = {w.x,w.y,w.z,w.w};
            #pragma unroll
            for (int i = 0; i < 4; i++)
                #pragma unroll
                for (int j = 0; j < 4; j++) acc[i][j] += av[i] * wv[j];
        }
        __syncthreads();
    }
    #pragma unroll
    for (int i = 0; i < 4; i++) {
        int row = rowBase + ty * 4 + i;
        #pragma unroll
        for (int j = 0; j < 4; j++) {
            int col = colBase + tx * 4 + j;
            C[(size_t)row * N + col] = acc[i][j] + bias[col];
        }
    }
}

// ---------------------------------------------------------------------------
// HMMA LSTM step. grid=128, block=256 (8 warps: wy=wid&3 M-tile, wx=wid>>2 N-half).
// D[64 x 32] = h[64,1024] @ WhT via bf16x3 split. A via smem+ldmatrix, B via
// one coalesced LDG.128 per split per k-step. Fused nonlinearity epilogue.
__global__ __launch_bounds__(256)
void lstm_step_mma(int t) {
    __shared__ __align__(16) char smA[2][8192];   // A hi / A lo, SW128-swizzled
    __shared__ float Ds[64][32];

    const int tid = threadIdx.x;
    const int lane = tid & 31;
    const int wid = tid >> 5;
    const int wy = wid & 3;          // M tile (16 rows)
    const int wx = wid >> 2;         // N half (16 cols)
    const int blk = blockIdx.x;

    const __nv_bfloat16* hh = g_hh[t & 1];
    const __nv_bfloat16* hl = g_hl[t & 1];

    const uint32_t uA0 = smem_u32(smA[0]);
    const uint32_t uA1 = smem_u32(smA[1]);
    // ldmatrix per-lane source: row = wy*16 + (lane&15), col-half = (lane>>4)*8
    const int lrow = wy * 16 + (lane & 15);
    const int lch  = (lane >> 4) * 8;

    float acc0[4] = {}, acc1[4] = {};

    // A-staging indices: 512 uint4 per split per chunk; thread does 2.
    const int c0 = tid, c1 = 256 + tid;
    const int row0 = c0 >> 3, q0 = c0 & 7;
    const int row1 = c1 >> 3, q1 = c1 & 7;
    const uint32_t off0 = SW128((uint32_t)(row0 * 128 + q0 * 16));
    const uint32_t off1 = SW128((uint32_t)(row1 * 128 + q1 * 16));

    for (int kc = 0; kc < 16; kc++) {
        const int kb = kc * 64;
        *(uint4*)(smA[0] + off0) = *(const uint4*)&hh[row0 * Hd + kb + q0 * 8];
        *(uint4*)(smA[0] + off1) = *(const uint4*)&hh[row1 * Hd + kb + q1 * 8];
        *(uint4*)(smA[1] + off0) = *(const uint4*)&hl[row0 * Hd + kb + q0 * 8];
        *(uint4*)(smA[1] + off1) = *(const uint4*)&hl[row1 * Hd + kb + q1 * 8];
        __syncthreads();

        #pragma unroll
        for (int ks = 0; ks < 4; ks++) {
            uint32_t offA = SW128((uint32_t)(lrow * 128 + (ks * 16 + lch) * 2));
            uint32_t ah[4], al[4];
            ldmatrix_x4(ah, uA0 + offA);
            ldmatrix_x4(al, uA1 + offA);

            size_t bidx = ((size_t)(blk * NKS + kc * 4 + ks) * 2 + wx) * 32 + lane;
            uint4 bh = g_Bfh[bidx];
            uint4 bl = g_Bfl[bidx];

            mma_bf16(acc0, ah, bh.x, bh.y);   // hi*hi  tile0
            mma_bf16(acc1, ah, bh.z, bh.w);   // hi*hi  tile1
            mma_bf16(acc0, ah, bl.x, bl.y);   // hi*lo
            mma_bf16(acc1, ah, bl.z, bl.w);
            mma_bf16(acc0, al, bh.x, bh.y);   // lo*hi
            mma_bf16(acc1, al, bh.z, bh.w);
        }
        __syncthreads();
    }

    // Scatter accumulators to smem: m16n8 frag -> (row=lane/4 [+8], col=2*(lane%4)[+1])
    {
        const int r = lane >> 2, cc = (lane & 3) * 2;
        const int m0 = wy * 16;
        const int n0 = wx * 16;
        Ds[m0 + r    ][n0 + 0 + cc    ] = acc0[0];
        Ds[m0 + r    ][n0 + 0 + cc + 1] = acc0[1];
        Ds[m0 + r + 8][n0 + 0 + cc    ] = acc0[2];
        Ds[m0 + r + 8][n0 + 0 + cc + 1] = acc0[3];
        Ds[m0 + r    ][n0 + 8 + cc    ] = acc1[0];
        Ds[m0 + r    ][n0 + 8 + cc + 1] = acc1[1];
        Ds[m0 + r + 8][n0 + 8 + cc    ] = acc1[2];
        Ds[m0 + r + 8][n0 + 8 + cc + 1] = acc1[3];
    }
    __syncthreads();

    // Nonlinearity: 512 outputs, 2 per thread
    const int jbase = blk * NJJ;
    #pragma unroll
    for (int u = 0; u < 2; u++) {
        int oi = tid * 2 + u;
        int b = oi >> 3, jj = oi & 7;
        const float* xpr = &g_xp[((size_t)b * Tt + t) * G4];
        float gi = Ds[b][0*8 + jj] + xpr[0 * Hd + jbase + jj];
        float gf = Ds[b][1*8 + jj] + xpr[1 * Hd + jbase + jj];
        float gg = Ds[b][2*8 + jj] + xpr[2 * Hd + jbase + jj];
        float go = Ds[b][3*8 + jj] + xpr[3 * Hd + jbase + jj];

        float si = 1.f / (1.f + expf(-gi));
        float sf = 1.f / (1.f + expf(-gf));
        float so = 1.f / (1.f + expf(-go));
        float tg = tanhf(gg);

        int ci = b * Hd + jbase + jj;
        float cN = sf * g_c[ci] + si * tg;
        g_c[ci] = cN;
        float hN = so * tanhf(cN);
        g_hs[((size_t)b * Tt + t) * Hd + jbase + jj] = hN;
        __nv_bfloat16 hi = __float2bfloat16_rn(hN);
        g_hh[(t + 1) & 1][ci] = hi;
        g_hl[(t + 1) & 1][ci] = __float2bfloat16_rn(hN - __bfloat162float(hi));
    }
}

// ---------------------------------------------------------------------------
extern "C" void kernel_launch(void* const* d_in, const int* in_sizes, int n_in,
                              void* d_out, int out_size) {
    const float* xs = (const float*)d_in[0];
    const float* Wi = (const float*)d_in[1];
    const float* Wh = (const float*)d_in[2];
    const float* b  = (const float*)d_in[3];
    const float* Wo = (const float*)d_in[4];
    const float* bo = (const float*)d_in[5];
    float* out = (float*)d_out;

    float *xp_p = nullptr, *hs_p = nullptr;
    cudaGetSymbolAddress((void**)&xp_p, g_xp);
    cudaGetSymbolAddress((void**)&hs_p, g_hs);

    // 0) init state + weight fragment scatter
    zero_state<<<(Bb * Hd + 255) / 256, 256>>>();
    prep_Bfrag<<<(NBLK * NKS * 2 * 32) / 256, 256>>>(Wh);

    // 1) xp = xs @ Wi + b
    {
        dim3 grid(G4 / 64, Mrows / 64);
        gemm_bias<INd><<<grid, 256>>>(xs, Wi, b, xp_p, G4);
    }

    // 2) 256 recurrent steps on HMMA
    for (int t = 0; t < Tt; t++)
        lstm_step_mma<<<NBLK, 256>>>(t);

    // 3) logits = hs @ Wo + bo
    {
        dim3 grid(OUTd / 64, Mrows / 64);
        gemm_bias<Hd><<<grid, 256>>>(hs_p, Wo, bo, out, OUTd);
    }
}

// round 6
// speedup vs baseline: 1.9075x; 1.1702x over previous
#include <cuda_runtime.h>
#include <cuda_bf16.h>
#include <math.h>
#include <stdint.h>

#define Bb   64
#define Tt   256
#define INd  512
#define Hd   1024
#define OUTd 512
#define G4   (4*Hd)        // 4096
#define Mrows (Bb*Tt)      // 16384

#define NBLK 128           // persistent blocks; each owns 8 hidden cols (x4 gates = N=32)
#define NJJ  8             // hidden cols per block
#define NKS  64            // k16 steps (K=1024)

// ---------------- scratch (device globals) ----------------
__device__ float g_xp[(size_t)Mrows * G4];        // [B*T, 4H]
__device__ float g_hs[(size_t)Mrows * Hd];        // [B*T, H]
__device__ __nv_bfloat16 g_hh[2][Bb * Hd];        // h hi split (ping-pong)
__device__ __nv_bfloat16 g_hl[2][Bb * Hd];        // h lo split
__device__ unsigned g_bar;                        // grid barrier counter
// Wh pre-scattered into HMMA B-fragment order:
// [blk][s(=64)][wx(=2)][lane] -> uint4 {b0_t0, b1_t0, b0_t1, b1_t1}
__device__ uint4 g_Bfh[(size_t)NBLK * NKS * 2 * 32];
__device__ uint4 g_Bfl[(size_t)NBLK * NKS * 2 * 32];

#define SW128(b) ((b) ^ (((b) >> 3) & 0x70))
#define BIDX(s) ((((size_t)blk * NKS + (s)) * 2 + wx) * 32 + lane)

__device__ __forceinline__ uint32_t smem_u32(const void* p) {
    uint32_t a;
    asm("{ .reg .u64 t; cvta.to.shared.u64 t, %1; cvt.u32.u64 %0, t; }" : "=r"(a) : "l"(p));
    return a;
}
__device__ __forceinline__ void ldmatrix_x4(uint32_t* r, uint32_t addr) {
    asm volatile("ldmatrix.sync.aligned.m8n8.x4.shared.b16 {%0,%1,%2,%3}, [%4];"
                 : "=r"(r[0]), "=r"(r[1]), "=r"(r[2]), "=r"(r[3]) : "r"(addr));
}
__device__ __forceinline__ void mma_bf16(float* c, const uint32_t* a,
                                         uint32_t b0, uint32_t b1) {
    asm volatile(
        "mma.sync.aligned.m16n8k16.row.col.f32.bf16.bf16.f32 "
        "{%0,%1,%2,%3}, {%4,%5,%6,%7}, {%8,%9}, {%0,%1,%2,%3};"
        : "+f"(c[0]), "+f"(c[1]), "+f"(c[2]), "+f"(c[3])
        : "r"(a[0]), "r"(a[1]), "r"(a[2]), "r"(a[3]), "r"(b0), "r"(b1));
}
__device__ __forceinline__ uint4 ldg_cg(const void* p) {
    uint4 v;
    asm volatile("ld.global.cg.v4.u32 {%0,%1,%2,%3}, [%4];"
                 : "=r"(v.x), "=r"(v.y), "=r"(v.z), "=r"(v.w) : "l"(p));
    return v;
}
__device__ __forceinline__ uint32_t pack_bf16(float x, float y) {
    __nv_bfloat162 v = __floats2bfloat162_rn(x, y);
    return *(uint32_t*)&v;
}

// ---------------------------------------------------------------------------
__global__ void zero_state() {
    int i = blockIdx.x * blockDim.x + threadIdx.x;
    if (i == 0) g_bar = 0;
    if (i < Bb * Hd) {
        g_hh[0][i] = __float2bfloat16(0.f);
        g_hl[0][i] = __float2bfloat16(0.f);
    }
}

// ---------------------------------------------------------------------------
// Scatter Wh (fp32 [1024][4096]) into per-lane B-fragment order, bf16 hi/lo.
__global__ __launch_bounds__(256) void prep_Bfrag(const float* __restrict__ Wh) {
    int gid = blockIdx.x * blockDim.x + threadIdx.x;    // 0 .. 524287
    int lane = gid & 31;
    int wx   = (gid >> 5) & 1;
    int ks   = (gid >> 6) & 63;
    int blk  = gid >> 12;

    uint32_t outh[4], outl[4];
    #pragma unroll
    for (int t2 = 0; t2 < 2; t2++) {
        int loc = wx * 16 + t2 * 8 + (lane >> 2);       // local gate-col 0..31
        int g = loc >> 3, jj = loc & 7;
        int col = g * Hd + blk * NJJ + jj;              // global col in 4H
        int kb = ks * 16 + (lane & 3) * 2;
        float w0 = Wh[(size_t)(kb + 0) * G4 + col];
        float w1 = Wh[(size_t)(kb + 1) * G4 + col];
        float w8 = Wh[(size_t)(kb + 8) * G4 + col];
        float w9 = Wh[(size_t)(kb + 9) * G4 + col];
        float h0 = __bfloat162float(__float2bfloat16_rn(w0));
        float h1 = __bfloat162float(__float2bfloat16_rn(w1));
        float h8 = __bfloat162float(__float2bfloat16_rn(w8));
        float h9 = __bfloat162float(__float2bfloat16_rn(w9));
        outh[t2*2+0] = pack_bf16(h0, h1);
        outh[t2*2+1] = pack_bf16(h8, h9);
        outl[t2*2+0] = pack_bf16(w0 - h0, w1 - h1);
        outl[t2*2+1] = pack_bf16(w8 - h8, w9 - h9);
    }
    g_Bfh[gid] = make_uint4(outh[0], outh[1], outh[2], outh[3]);
    g_Bfl[gid] = make_uint4(outl[0], outl[1], outl[2], outl[3]);
}

// ---------------------------------------------------------------------------
// fp32 SIMT GEMM (unchanged): C = A@W + bias
template<int K>
__global__ __launch_bounds__(256)
void gemm_bias(const float* __restrict__ A, const float* __restrict__ W,
               const float* __restrict__ bias, float* __restrict__ C, int N) {
    __shared__ float As[64][68];
    __shared__ float Ws[64][68];
    const int tid = threadIdx.x;
    const int tx = tid & 15, ty = tid >> 4;
    const int rowBase = blockIdx.y * 64, colBase = blockIdx.x * 64;
    float acc[4][4] = {};
    for (int k0 = 0; k0 < K; k0 += 64) {
        #pragma unroll
        for (int r = 0; r < 4; r++) {
            int fi = r * 256 + tid; int row = fi >> 4; int q = fi & 15;
            float4 v = *(const float4*)&A[(size_t)(rowBase + row) * K + k0 + q * 4];
            As[q*4+0][row] = v.x; As[q*4+1][row] = v.y;
            As[q*4+2][row] = v.z; As[q*4+3][row] = v.w;
        }
        #pragma unroll
        for (int r = 0; r < 4; r++) {
            int fi = r * 256 + tid; int kk = fi >> 4; int q = fi & 15;
            *(float4*)&Ws[kk][q * 4] =
                *(const float4*)&W[(size_t)(k0 + kk) * N + colBase + q * 4];
        }
        __syncthreads();
        #pragma unroll 16
        for (int kk = 0; kk < 64; kk++) {
            float4 a = *(const float4*)&As[kk][ty * 4];
            float4 w = *(const float4*)&Ws[kk][tx * 4];
            float av[4] = {a.x,a.y,a.z,a.w}, wv[4] = {w.x,w.y,w.z,w.w};
            #pragma unroll
            for (int i = 0; i < 4; i++)
                #pragma unroll
                for (int j = 0; j < 4; j++) acc[i][j] += av[i] * wv[j];
        }
        __syncthreads();
    }
    #pragma unroll
    for (int i = 0; i < 4; i++) {
        int row = rowBase + ty * 4 + i;
        #pragma unroll
        for (int j = 0; j < 4; j++) {
            int col = colBase + tx * 4 + j;
            C[(size_t)row * N + col] = acc[i][j] + bias[col];
        }
    }
}

// ---------------------------------------------------------------------------
// Persistent HMMA LSTM: one launch, 256 steps, atomic grid barrier per step.
// grid=128, block=256 (8 warps: wy=wid&3 M-tile, wx=wid>>2 N-half).
// Per step: D[64x32] = h @ WhT via bf16x3 split. A double-buffered in smem,
// B 2-deep prefetch ring (L1-resident after step 1). c-state in registers.
__global__ __launch_bounds__(256)
void lstm_persist() {
    __shared__ __align__(16) char smA[2][2][8192];   // [buf][hi/lo], SW128
    __shared__ float Ds[64][32];

    const int tid = threadIdx.x;
    const int lane = tid & 31;
    const int wid = tid >> 5;
    const int wy = wid & 3;          // M tile (16 rows)
    const int wx = wid >> 2;         // N half (16 cols)
    const int blk = blockIdx.x;
    const int jbase = blk * NJJ;

    const int lrow = wy * 16 + (lane & 15);
    const int lch  = (lane >> 4) * 8;

    // A-staging: thread loads 2 uint4 per split per chunk
    const int c0 = tid, c1 = 256 + tid;
    const int row0 = c0 >> 3, q0 = c0 & 7;
    const int row1 = c1 >> 3, q1 = c1 & 7;
    const uint32_t off0 = SW128((uint32_t)(row0 * 128 + q0 * 16));
    const uint32_t off1 = SW128((uint32_t)(row1 * 128 + q1 * 16));

    uint32_t uA[2][2];
    uA[0][0] = smem_u32(smA[0][0]); uA[0][1] = smem_u32(smA[0][1]);
    uA[1][0] = smem_u32(smA[1][0]); uA[1][1] = smem_u32(smA[1][1]);

    // epilogue ownership: 2 outputs per thread, fixed across steps
    const int ob0 = (tid * 2) >> 3,     oj0 = (tid * 2) & 7;
    const int ob1 = (tid * 2 + 1) >> 3, oj1 = (tid * 2 + 1) & 7;
    float c_r[2] = {0.f, 0.f};          // cell state lives in registers

    for (int t = 0; t < Tt; t++) {
        const __nv_bfloat16* hh = g_hh[t & 1];
        const __nv_bfloat16* hl = g_hl[t & 1];

        // prefetch xp for this step (hidden under the MMA loop)
        float xg[2][4];
        #pragma unroll
        for (int g = 0; g < 4; g++) {
            xg[0][g] = g_xp[((size_t)ob0 * Tt + t) * G4 + g * Hd + jbase + oj0];
            xg[1][g] = g_xp[((size_t)ob1 * Tt + t) * G4 + g * Hd + jbase + oj1];
        }

        // chunk 0 of A + first two B fragments
        uint4 a0h = ldg_cg(&hh[row0 * Hd + q0 * 8]);
        uint4 a1h = ldg_cg(&hh[row1 * Hd + q1 * 8]);
        uint4 a0l = ldg_cg(&hl[row0 * Hd + q0 * 8]);
        uint4 a1l = ldg_cg(&hl[row1 * Hd + q1 * 8]);
        uint4 BHr[2], BLr[2];
        BHr[0] = g_Bfh[BIDX(0)]; BLr[0] = g_Bfl[BIDX(0)];
        BHr[1] = g_Bfh[BIDX(1)]; BLr[1] = g_Bfl[BIDX(1)];

        *(uint4*)(smA[0][0] + off0) = a0h;
        *(uint4*)(smA[0][0] + off1) = a1h;
        *(uint4*)(smA[0][1] + off0) = a0l;
        *(uint4*)(smA[0][1] + off1) = a1l;
        __syncthreads();

        float acc0[4] = {}, acc1[4] = {};

        for (int kc = 0; kc < 16; kc++) {
            const int kn = kc + 1;
            if (kn < 16) {   // next A chunk LDGs issue under this chunk's MMAs
                a0h = ldg_cg(&hh[row0 * Hd + kn * 64 + q0 * 8]);
                a1h = ldg_cg(&hh[row1 * Hd + kn * 64 + q1 * 8]);
                a0l = ldg_cg(&hl[row0 * Hd + kn * 64 + q0 * 8]);
                a1l = ldg_cg(&hl[row1 * Hd + kn * 64 + q1 * 8]);
            }
            const uint32_t uh = uA[kc & 1][0], ul = uA[kc & 1][1];

            #pragma unroll
            for (int ks = 0; ks < 4; ks++) {
                const int s = kc * 4 + ks;
                uint4 bh = BHr[ks & 1], bl = BLr[ks & 1];
                if (s + 2 < NKS) {    // 2-deep B prefetch
                    BHr[ks & 1] = g_Bfh[BIDX(s + 2)];
                    BLr[ks & 1] = g_Bfl[BIDX(s + 2)];
                }
                uint32_t offA = SW128((uint32_t)(lrow * 128 + (ks * 16 + lch) * 2));
                uint32_t ah[4], al[4];
                ldmatrix_x4(ah, uh + offA);
                ldmatrix_x4(al, ul + offA);

                mma_bf16(acc0, ah, bh.x, bh.y);
                mma_bf16(acc1, ah, bh.z, bh.w);
                mma_bf16(acc0, ah, bl.x, bl.y);
                mma_bf16(acc1, ah, bl.z, bl.w);
                mma_bf16(acc0, al, bh.x, bh.y);
                mma_bf16(acc1, al, bh.z, bh.w);
            }

            if (kn < 16) {
                char* d0 = smA[kn & 1][0];
                char* d1 = smA[kn & 1][1];
                *(uint4*)(d0 + off0) = a0h;
                *(uint4*)(d0 + off1) = a1h;
                *(uint4*)(d1 + off0) = a0l;
                *(uint4*)(d1 + off1) = a1l;
            }
            __syncthreads();
        }

        // scatter accumulators to Ds
        {
            const int r = lane >> 2, cc = (lane & 3) * 2;
            const int m0 = wy * 16, n0 = wx * 16;
            Ds[m0 + r    ][n0 + 0 + cc    ] = acc0[0];
            Ds[m0 + r    ][n0 + 0 + cc + 1] = acc0[1];
            Ds[m0 + r + 8][n0 + 0 + cc    ] = acc0[2];
            Ds[m0 + r + 8][n0 + 0 + cc + 1] = acc0[3];
            Ds[m0 + r    ][n0 + 8 + cc    ] = acc1[0];
            Ds[m0 + r    ][n0 + 8 + cc + 1] = acc1[1];
            Ds[m0 + r + 8][n0 + 8 + cc    ] = acc1[2];
            Ds[m0 + r + 8][n0 + 8 + cc + 1] = acc1[3];
        }
        __syncthreads();

        // fused nonlinearity; c in registers
        #pragma unroll
        for (int u = 0; u < 2; u++) {
            const int b  = u ? ob1 : ob0;
            const int jj = u ? oj1 : oj0;
            float gi = Ds[b][0*8 + jj] + xg[u][0];
            float gf = Ds[b][1*8 + jj] + xg[u][1];
            float gg = Ds[b][2*8 + jj] + xg[u][2];
            float go = Ds[b][3*8 + jj] + xg[u][3];

            float si = 1.f / (1.f + expf(-gi));
            float sf = 1.f / (1.f + expf(-gf));
            float so = 1.f / (1.f + expf(-go));
            float tg = tanhf(gg);

            float cN = sf * c_r[u] + si * tg;
            c_r[u] = cN;
            float hN = so * tanhf(cN);

            const int ci = b * Hd + jbase + jj;
            g_hs[((size_t)b * Tt + t) * Hd + jbase + jj] = hN;
            __nv_bfloat16 hi = __float2bfloat16_rn(hN);
            g_hh[(t + 1) & 1][ci] = hi;
            g_hl[(t + 1) & 1][ci] = __float2bfloat16_rn(hN - __bfloat162float(hi));
        }

        // grid barrier (monotonic counter; g_bar zeroed per launch)
        __syncthreads();
        if (tid == 0) {
            __threadfence();
            atomicAdd(&g_bar, 1u);
            const unsigned tgt = (unsigned)(t + 1) * (unsigned)NBLK;
            while (atomicAdd(&g_bar, 0u) < tgt) { }
            __threadfence();
        }
        __syncthreads();
    }
}

// ---------------------------------------------------------------------------
extern "C" void kernel_launch(void* const* d_in, const int* in_sizes, int n_in,
                              void* d_out, int out_size) {
    const float* xs = (const float*)d_in[0];
    const float* Wi = (const float*)d_in[1];
    const float* Wh = (const float*)d_in[2];
    const float* b  = (const float*)d_in[3];
    const float* Wo = (const float*)d_in[4];
    const float* bo = (const float*)d_in[5];
    float* out = (float*)d_out;

    float *xp_p = nullptr, *hs_p = nullptr;
    cudaGetSymbolAddress((void**)&xp_p, g_xp);
    cudaGetSymbolAddress((void**)&hs_p, g_hs);

    // 0) init state (+barrier) + weight fragment scatter
    zero_state<<<(Bb * Hd + 255) / 256, 256>>>();
    prep_Bfrag<<<(NBLK * NKS * 2 * 32) / 256, 256>>>(Wh);

    // 1) xp = xs @ Wi + b
    {
        dim3 grid(G4 / 64, Mrows / 64);
        gemm_bias<INd><<<grid, 256>>>(xs, Wi, b, xp_p, G4);
    }

    // 2) recurrence: one persistent launch, 256 steps inside
    lstm_persist<<<NBLK, 256>>>();

    // 3) logits = hs @ Wo + bo
    {
        dim3 grid(OUTd / 64, Mrows / 64);
        gemm_bias<Hd><<<grid, 256>>>(hs_p, Wo, bo, out, OUTd);
    }
}

// round 7
// speedup vs baseline: 2.5139x; 1.3179x over previous
#include <cuda_runtime.h>
#include <cuda_bf16.h>
#include <math.h>
#include <stdint.h>

#define Bb   64
#define Tt   256
#define INd  512
#define Hd   1024
#define OUTd 512
#define G4   (4*Hd)        // 4096
#define Mrows (Bb*Tt)      // 16384

#define NBLK 128           // persistent blocks; each owns 8 hidden cols (x4 gates = N=32)
#define NJJ  8             // hidden cols per block
#define NKS  64            // k16 steps (K=1024)

// ---------------- scratch (device globals) ----------------
__device__ float g_xp[(size_t)Mrows * G4];          // [B*T, 4H]
__device__ __nv_bfloat16 g_xsh[(size_t)Mrows * INd];  // xs hi split
__device__ __nv_bfloat16 g_xsl[(size_t)Mrows * INd];  // xs lo split
__device__ __nv_bfloat16 g_hsh[(size_t)Mrows * Hd]; // hs hi split
__device__ __nv_bfloat16 g_hsl[(size_t)Mrows * Hd]; // hs lo split
__device__ __nv_bfloat16 g_hh[2][Bb * Hd];          // h hi (ping-pong)
__device__ __nv_bfloat16 g_hl[2][Bb * Hd];          // h lo
__device__ unsigned g_bar;                          // grid barrier counter
// Wh pre-scattered into HMMA B-fragment order (recurrence):
__device__ uint4 g_Bfh[(size_t)NBLK * NKS * 2 * 32];
__device__ uint4 g_Bfl[(size_t)NBLK * NKS * 2 * 32];
// Wi / Wo fragment arrays: [cg][s][lane][2] uint4, hi/lo
#define WI_CG (G4/32)      // 128
#define WI_KS (INd/16)     // 32
#define WO_CG (OUTd/32)    // 16
#define WO_KS (Hd/16)      // 64
__device__ uint4 g_WiFh[(size_t)WI_CG * WI_KS * 32 * 2];
__device__ uint4 g_WiFl[(size_t)WI_CG * WI_KS * 32 * 2];
__device__ uint4 g_WoFh[(size_t)WO_CG * WO_KS * 32 * 2];
__device__ uint4 g_WoFl[(size_t)WO_CG * WO_KS * 32 * 2];

#define SW128(b) ((b) ^ (((b) >> 3) & 0x70))
#define BIDX(s) ((((size_t)blk * NKS + (s)) * 2 + wx) * 32 + lane)

__device__ __forceinline__ uint32_t smem_u32(const void* p) {
    uint32_t a;
    asm("{ .reg .u64 t; cvta.to.shared.u64 t, %1; cvt.u32.u64 %0, t; }" : "=r"(a) : "l"(p));
    return a;
}
__device__ __forceinline__ void ldmatrix_x4(uint32_t* r, uint32_t addr) {
    asm volatile("ldmatrix.sync.aligned.m8n8.x4.shared.b16 {%0,%1,%2,%3}, [%4];"
                 : "=r"(r[0]), "=r"(r[1]), "=r"(r[2]), "=r"(r[3]) : "r"(addr));
}
__device__ __forceinline__ void mma_bf16(float* c, const uint32_t* a,
                                         uint32_t b0, uint32_t b1) {
    asm volatile(
        "mma.sync.aligned.m16n8k16.row.col.f32.bf16.bf16.f32 "
        "{%0,%1,%2,%3}, {%4,%5,%6,%7}, {%8,%9}, {%0,%1,%2,%3};"
        : "+f"(c[0]), "+f"(c[1]), "+f"(c[2]), "+f"(c[3])
        : "r"(a[0]), "r"(a[1]), "r"(a[2]), "r"(a[3]), "r"(b0), "r"(b1));
}
__device__ __forceinline__ uint4 ldg_cg(const void* p) {
    uint4 v;
    asm volatile("ld.global.cg.v4.u32 {%0,%1,%2,%3}, [%4];"
                 : "=r"(v.x), "=r"(v.y), "=r"(v.z), "=r"(v.w) : "l"(p));
    return v;
}
__device__ __forceinline__ uint32_t pack_bf16(float x, float y) {
    __nv_bfloat162 v = __floats2bfloat162_rn(x, y);
    return *(uint32_t*)&v;
}
#define CP_ASYNC16(sm, gp) \
    asm volatile("cp.async.cg.shared.global [%0], [%1], 16;" :: "r"(sm), "l"(gp))
#define CP_COMMIT() asm volatile("cp.async.commit_group;" ::: "memory")
#define CP_WAIT(n)  asm volatile("cp.async.wait_group %0;" :: "n"(n) : "memory")

// ---------------------------------------------------------------------------
__global__ void zero_state() {
    int i = blockIdx.x * blockDim.x + threadIdx.x;
    if (i == 0) g_bar = 0;
    if (i < Bb * Hd) {
        g_hh[0][i] = __float2bfloat16(0.f);
        g_hl[0][i] = __float2bfloat16(0.f);
    }
}

// split xs into bf16 hi/lo
__global__ __launch_bounds__(256) void split_xs(const float* __restrict__ xs) {
    size_t i = (size_t)blockIdx.x * blockDim.x + threadIdx.x;
    if (i < (size_t)Mrows * INd) {
        float v = xs[i];
        __nv_bfloat16 hi = __float2bfloat16_rn(v);
        g_xsh[i] = hi;
        g_xsl[i] = __float2bfloat16_rn(v - __bfloat162float(hi));
    }
}

// ---------------------------------------------------------------------------
// Scatter Wh into recurrence B-fragment order (unchanged from R4/R5).
__global__ __launch_bounds__(256) void prep_Bfrag(const float* __restrict__ Wh) {
    int gid = blockIdx.x * blockDim.x + threadIdx.x;
    int lane = gid & 31;
    int wx   = (gid >> 5) & 1;
    int ks   = (gid >> 6) & 63;
    int blk  = gid >> 12;

    uint32_t outh[4], outl[4];
    #pragma unroll
    for (int t2 = 0; t2 < 2; t2++) {
        int loc = wx * 16 + t2 * 8 + (lane >> 2);
        int g = loc >> 3, jj = loc & 7;
        int col = g * Hd + blk * NJJ + jj;
        int kb = ks * 16 + (lane & 3) * 2;
        float w0 = Wh[(size_t)(kb + 0) * G4 + col];
        float w1 = Wh[(size_t)(kb + 1) * G4 + col];
        float w8 = Wh[(size_t)(kb + 8) * G4 + col];
        float w9 = Wh[(size_t)(kb + 9) * G4 + col];
        float h0 = __bfloat162float(__float2bfloat16_rn(w0));
        float h1 = __bfloat162float(__float2bfloat16_rn(w1));
        float h8 = __bfloat162float(__float2bfloat16_rn(w8));
        float h9 = __bfloat162float(__float2bfloat16_rn(w9));
        outh[t2*2+0] = pack_bf16(h0, h1);
        outh[t2*2+1] = pack_bf16(h8, h9);
        outl[t2*2+0] = pack_bf16(w0 - h0, w1 - h1);
        outl[t2*2+1] = pack_bf16(w8 - h8, w9 - h9);
    }
    g_Bfh[gid] = make_uint4(outh[0], outh[1], outh[2], outh[3]);
    g_Bfl[gid] = make_uint4(outl[0], outl[1], outl[2], outl[3]);
}

// ---------------------------------------------------------------------------
// Scatter a [K][N] weight into GEMM B-fragment order:
// out[((cg*KS + s)*32 + lane)*2 + j] = {t(2j).b0, t(2j).b1, t(2j+1).b0, t(2j+1).b1}
// where tile t covers cols cg*32 + t*8, b0 = pack(W[k0+2c][n], W[k0+2c+1][n]),
// b1 = pack(W[k0+8+2c][n], W[k0+9+2c][n]), c = lane%4, n-within-tile = lane/4.
__global__ __launch_bounds__(256)
void prep_Wfrag(const float* __restrict__ W, int N, int KS,
                uint4* __restrict__ outh_arr, uint4* __restrict__ outl_arr) {
    int gid = blockIdx.x * blockDim.x + threadIdx.x;   // (cg*KS+s)*32 + lane
    int lane = gid & 31;
    int s    = (gid >> 5) % KS;
    int cg   = (gid >> 5) / KS;

    const int k0 = s * 16 + (lane & 3) * 2;
    #pragma unroll
    for (int j = 0; j < 2; j++) {
        uint32_t oh[4], ol[4];
        #pragma unroll
        for (int tt = 0; tt < 2; tt++) {
            int col = cg * 32 + (j * 2 + tt) * 8 + (lane >> 2);
            float w0 = W[(size_t)(k0 + 0) * N + col];
            float w1 = W[(size_t)(k0 + 1) * N + col];
            float w8 = W[(size_t)(k0 + 8) * N + col];
            float w9 = W[(size_t)(k0 + 9) * N + col];
            float h0 = __bfloat162float(__float2bfloat16_rn(w0));
            float h1 = __bfloat162float(__float2bfloat16_rn(w1));
            float h8 = __bfloat162float(__float2bfloat16_rn(w8));
            float h9 = __bfloat162float(__float2bfloat16_rn(w9));
            oh[tt*2+0] = pack_bf16(h0, h1);
            oh[tt*2+1] = pack_bf16(h8, h9);
            ol[tt*2+0] = pack_bf16(w0 - h0, w1 - h1);
            ol[tt*2+1] = pack_bf16(w8 - h8, w9 - h9);
        }
        outh_arr[(size_t)gid * 2 + j] = make_uint4(oh[0], oh[1], oh[2], oh[3]);
        outl_arr[(size_t)gid * 2 + j] = make_uint4(ol[0], ol[1], ol[2], ol[3]);
    }
}

// ---------------------------------------------------------------------------
// bf16x3-split HMMA GEMM: C[M,N] = Ah+Al @ W + bias.
// Block tile 128x64, 8 warps (wy 0..3 over M, wn 0..1 over N-halves of 32).
// A double-buffered in smem via cp.async; B fragments LDG'd with 2-deep ring.
template<int K>
__global__ __launch_bounds__(256)
void gemm_mma(const __nv_bfloat16* __restrict__ Ah,
              const __nv_bfloat16* __restrict__ Al,
              const uint4* __restrict__ BfH, const uint4* __restrict__ BfL,
              const float* __restrict__ bias, float* __restrict__ C, int N) {
    constexpr int KS = K / 16;
    constexpr int NC = K / 64;
    __shared__ __align__(16) char smA[2][2][16384];   // [buf][hi/lo] 128r x 64 bf16

    const int tid  = threadIdx.x;
    const int lane = tid & 31;
    const int wid  = tid >> 5;
    const int wy   = wid & 3;
    const int wn   = wid >> 2;
    const int rowBase = blockIdx.y * 128;
    const int colBase = blockIdx.x * 64;
    const int cg = blockIdx.x * 2 + wn;

    const uint32_t uA[2][2] = {
        { smem_u32(smA[0][0]), smem_u32(smA[0][1]) },
        { smem_u32(smA[1][0]), smem_u32(smA[1][1]) } };

    // cp.async staging: 1024 uint4 per split per chunk; 4 per thread per split
    int rowi[4], qi[4]; uint32_t offi[4];
    #pragma unroll
    for (int i = 0; i < 4; i++) {
        int idx = i * 256 + tid;
        rowi[i] = idx >> 3; qi[i] = idx & 7;
        offi[i] = SW128((uint32_t)(rowi[i] * 128 + qi[i] * 16));
    }
    #define ISSUE_A(buf, kb)                                                     \
        do {                                                                     \
            _Pragma("unroll")                                                    \
            for (int i = 0; i < 4; i++) {                                        \
                CP_ASYNC16(uA[buf][0] + offi[i],                                 \
                    &Ah[(size_t)(rowBase + rowi[i]) * K + (kb) + qi[i] * 8]);    \
                CP_ASYNC16(uA[buf][1] + offi[i],                                 \
                    &Al[(size_t)(rowBase + rowi[i]) * K + (kb) + qi[i] * 8]);    \
            }                                                                    \
            CP_COMMIT();                                                         \
        } while (0)

    float acc[2][4][4] = {};
    const int lr = lane & 15, lch = (lane >> 4) * 8;

    // B fragment ring: 2-deep, 2 uint4 per split per kstep
    const size_t bbase = ((size_t)cg * KS) * 64 + lane * 2;
    uint4 BH[2][2], BL[2][2];
    #pragma unroll
    for (int s = 0; s < 2; s++) {
        BH[s][0] = BfH[bbase + s * 64 + 0];
        BH[s][1] = BfH[bbase + s * 64 + 1];
        BL[s][0] = BfL[bbase + s * 64 + 0];
        BL[s][1] = BfL[bbase + s * 64 + 1];
    }

    ISSUE_A(0, 0);

    for (int kc = 0; kc < NC; kc++) {
        if (kc + 1 < NC) { ISSUE_A((kc + 1) & 1, (kc + 1) * 64); CP_WAIT(1); }
        else             { CP_WAIT(0); }
        __syncthreads();

        const uint32_t uh = uA[kc & 1][0], ul = uA[kc & 1][1];
        #pragma unroll
        for (int ks = 0; ks < 4; ks++) {
            const int s = kc * 4 + ks;
            uint4 bh0 = BH[ks & 1][0], bh1 = BH[ks & 1][1];
            uint4 bl0 = BL[ks & 1][0], bl1 = BL[ks & 1][1];
            if (s + 2 < KS) {
                BH[ks & 1][0] = BfH[bbase + (size_t)(s + 2) * 64 + 0];
                BH[ks & 1][1] = BfH[bbase + (size_t)(s + 2) * 64 + 1];
                BL[ks & 1][0] = BfL[bbase + (size_t)(s + 2) * 64 + 0];
                BL[ks & 1][1] = BfL[bbase + (size_t)(s + 2) * 64 + 1];
            }
            #pragma unroll
            for (int mt = 0; mt < 2; mt++) {
                const int lrow = wy * 32 + mt * 16 + lr;
                uint32_t offA = SW128((uint32_t)(lrow * 128 + (ks * 16 + lch) * 2));
                uint32_t ah[4], al[4];
                ldmatrix_x4(ah, uh + offA);
                ldmatrix_x4(al, ul + offA);

                mma_bf16(acc[mt][0], ah, bh0.x, bh0.y);
                mma_bf16(acc[mt][1], ah, bh0.z, bh0.w);
                mma_bf16(acc[mt][2], ah, bh1.x, bh1.y);
                mma_bf16(acc[mt][3], ah, bh1.z, bh1.w);
                mma_bf16(acc[mt][0], al, bh0.x, bh0.y);
                mma_bf16(acc[mt][1], al, bh0.z, bh0.w);
                mma_bf16(acc[mt][2], al, bh1.x, bh1.y);
                mma_bf16(acc[mt][3], al, bh1.z, bh1.w);
                mma_bf16(acc[mt][0], ah, bl0.x, bl0.y);
                mma_bf16(acc[mt][1], ah, bl0.z, bl0.w);
                mma_bf16(acc[mt][2], ah, bl1.x, bl1.y);
                mma_bf16(acc[mt][3], ah, bl1.z, bl1.w);
            }
        }
        __syncthreads();
    }

    // epilogue: bias + store (thread holds c[m][n], c[m][n+1], c[m+8][n], ...)
    const int r = lane >> 2, cc = (lane & 3) * 2;
    #pragma unroll
    for (int mt = 0; mt < 2; mt++) {
        const int m = rowBase + wy * 32 + mt * 16 + r;
        #pragma unroll
        for (int nt = 0; nt < 4; nt++) {
            const int n = colBase + wn * 32 + nt * 8 + cc;
            float b0 = bias[n], b1 = bias[n + 1];
            *(float2*)&C[(size_t)m * N + n] =
                make_float2(acc[mt][nt][0] + b0, acc[mt][nt][1] + b1);
            *(float2*)&C[(size_t)(m + 8) * N + n] =
                make_float2(acc[mt][nt][2] + b0, acc[mt][nt][3] + b1);
        }
    }
    #undef ISSUE_A
}

// ---------------------------------------------------------------------------
// Persistent HMMA LSTM (unchanged except epilogue writes hs as bf16 splits).
__global__ __launch_bounds__(256)
void lstm_persist() {
    __shared__ __align__(16) char smA[2][2][8192];
    __shared__ float Ds[64][32];

    const int tid = threadIdx.x;
    const int lane = tid & 31;
    const int wid = tid >> 5;
    const int wy = wid & 3;
    const int wx = wid >> 2;
    const int blk = blockIdx.x;
    const int jbase = blk * NJJ;

    const int lrow = wy * 16 + (lane & 15);
    const int lch  = (lane >> 4) * 8;

    const int c0 = tid, c1 = 256 + tid;
    const int row0 = c0 >> 3, q0 = c0 & 7;
    const int row1 = c1 >> 3, q1 = c1 & 7;
    const uint32_t off0 = SW128((uint32_t)(row0 * 128 + q0 * 16));
    const uint32_t off1 = SW128((uint32_t)(row1 * 128 + q1 * 16));

    uint32_t uA[2][2];
    uA[0][0] = smem_u32(smA[0][0]); uA[0][1] = smem_u32(smA[0][1]);
    uA[1][0] = smem_u32(smA[1][0]); uA[1][1] = smem_u32(smA[1][1]);

    const int ob0 = (tid * 2) >> 3,     oj0 = (tid * 2) & 7;
    const int ob1 = (tid * 2 + 1) >> 3, oj1 = (tid * 2 + 1) & 7;
    float c_r[2] = {0.f, 0.f};

    for (int t = 0; t < Tt; t++) {
        const __nv_bfloat16* hh = g_hh[t & 1];
        const __nv_bfloat16* hl = g_hl[t & 1];

        float xg[2][4];
        #pragma unroll
        for (int g = 0; g < 4; g++) {
            xg[0][g] = g_xp[((size_t)ob0 * Tt + t) * G4 + g * Hd + jbase + oj0];
            xg[1][g] = g_xp[((size_t)ob1 * Tt + t) * G4 + g * Hd + jbase + oj1];
        }

        uint4 a0h = ldg_cg(&hh[row0 * Hd + q0 * 8]);
        uint4 a1h = ldg_cg(&hh[row1 * Hd + q1 * 8]);
        uint4 a0l = ldg_cg(&hl[row0 * Hd + q0 * 8]);
        uint4 a1l = ldg_cg(&hl[row1 * Hd + q1 * 8]);
        uint4 BHr[2], BLr[2];
        BHr[0] = g_Bfh[BIDX(0)]; BLr[0] = g_Bfl[BIDX(0)];
        BHr[1] = g_Bfh[BIDX(1)]; BLr[1] = g_Bfl[BIDX(1)];

        *(uint4*)(smA[0][0] + off0) = a0h;
        *(uint4*)(smA[0][0] + off1) = a1h;
        *(uint4*)(smA[0][1] + off0) = a0l;
        *(uint4*)(smA[0][1] + off1) = a1l;
        __syncthreads();

        float acc0[4] = {}, acc1[4] = {};

        for (int kc = 0; kc < 16; kc++) {
            const int kn = kc + 1;
            if (kn < 16) {
                a0h = ldg_cg(&hh[row0 * Hd + kn * 64 + q0 * 8]);
                a1h = ldg_cg(&hh[row1 * Hd + kn * 64 + q1 * 8]);
                a0l = ldg_cg(&hl[row0 * Hd + kn * 64 + q0 * 8]);
                a1l = ldg_cg(&hl[row1 * Hd + kn * 64 + q1 * 8]);
            }
            const uint32_t uh = uA[kc & 1][0], ul = uA[kc & 1][1];

            #pragma unroll
            for (int ks = 0; ks < 4; ks++) {
                const int s = kc * 4 + ks;
                uint4 bh = BHr[ks & 1], bl = BLr[ks & 1];
                if (s + 2 < NKS) {
                    BHr[ks & 1] = g_Bfh[BIDX(s + 2)];
                    BLr[ks & 1] = g_Bfl[BIDX(s + 2)];
                }
                uint32_t offA = SW128((uint32_t)(lrow * 128 + (ks * 16 + lch) * 2));
                uint32_t ah[4], al[4];
                ldmatrix_x4(ah, uh + offA);
                ldmatrix_x4(al, ul + offA);

                mma_bf16(acc0, ah, bh.x, bh.y);
                mma_bf16(acc1, ah, bh.z, bh.w);
                mma_bf16(acc0, ah, bl.x, bl.y);
                mma_bf16(acc1, ah, bl.z, bl.w);
                mma_bf16(acc0, al, bh.x, bh.y);
                mma_bf16(acc1, al, bh.z, bh.w);
            }

            if (kn < 16) {
                char* d0 = smA[kn & 1][0];
                char* d1 = smA[kn & 1][1];
                *(uint4*)(d0 + off0) = a0h;
                *(uint4*)(d0 + off1) = a1h;
                *(uint4*)(d1 + off0) = a0l;
                *(uint4*)(d1 + off1) = a1l;
            }
            __syncthreads();
        }

        {
            const int r = lane >> 2, cc = (lane & 3) * 2;
            const int m0 = wy * 16, n0 = wx * 16;
            Ds[m0 + r    ][n0 + 0 + cc    ] = acc0[0];
            Ds[m0 + r    ][n0 + 0 + cc + 1] = acc0[1];
            Ds[m0 + r + 8][n0 + 0 + cc    ] = acc0[2];
            Ds[m0 + r + 8][n0 + 0 + cc + 1] = acc0[3];
            Ds[m0 + r    ][n0 + 8 + cc    ] = acc1[0];
            Ds[m0 + r    ][n0 + 8 + cc + 1] = acc1[1];
            Ds[m0 + r + 8][n0 + 8 + cc    ] = acc1[2];
            Ds[m0 + r + 8][n0 + 8 + cc + 1] = acc1[3];
        }
        __syncthreads();

        #pragma unroll
        for (int u = 0; u < 2; u++) {
            const int b  = u ? ob1 : ob0;
            const int jj = u ? oj1 : oj0;
            float gi = Ds[b][0*8 + jj] + xg[u][0];
            float gf = Ds[b][1*8 + jj] + xg[u][1];
            float gg = Ds[b][2*8 + jj] + xg[u][2];
            float go = Ds[b][3*8 + jj] + xg[u][3];

            float si = 1.f / (1.f + expf(-gi));
            float sf = 1.f / (1.f + expf(-gf));
            float so = 1.f / (1.f + expf(-go));
            float tg = tanhf(gg);

            float cN = sf * c_r[u] + si * tg;
            c_r[u] = cN;
            float hN = so * tanhf(cN);

            const int ci = b * Hd + jbase + jj;
            __nv_bfloat16 hi = __float2bfloat16_rn(hN);
            __nv_bfloat16 lo = __float2bfloat16_rn(hN - __bfloat162float(hi));
            g_hh[(t + 1) & 1][ci] = hi;
            g_hl[(t + 1) & 1][ci] = lo;
            const size_t hsi = ((size_t)b * Tt + t) * Hd + jbase + jj;
            g_hsh[hsi] = hi;
            g_hsl[hsi] = lo;
        }

        __syncthreads();
        if (tid == 0) {
            __threadfence();
            atomicAdd(&g_bar, 1u);
            const unsigned tgt = (unsigned)(t + 1) * (unsigned)NBLK;
            while (atomicAdd(&g_bar, 0u) < tgt) { }
            __threadfence();
        }
        __syncthreads();
    }
}

// ---------------------------------------------------------------------------
extern "C" void kernel_launch(void* const* d_in, const int* in_sizes, int n_in,
                              void* d_out, int out_size) {
    const float* xs = (const float*)d_in[0];
    const float* Wi = (const float*)d_in[1];
    const float* Wh = (const float*)d_in[2];
    const float* b  = (const float*)d_in[3];
    const float* Wo = (const float*)d_in[4];
    const float* bo = (const float*)d_in[5];
    float* out = (float*)d_out;

    float* xp_p = nullptr;
    __nv_bfloat16 *xsh_p = nullptr, *xsl_p = nullptr, *hsh_p = nullptr, *hsl_p = nullptr;
    uint4 *wifh = nullptr, *wifl = nullptr, *wofh = nullptr, *wofl = nullptr;
    cudaGetSymbolAddress((void**)&xp_p, g_xp);
    cudaGetSymbolAddress((void**)&xsh_p, g_xsh);
    cudaGetSymbolAddress((void**)&xsl_p, g_xsl);
    cudaGetSymbolAddress((void**)&hsh_p, g_hsh);
    cudaGetSymbolAddress((void**)&hsl_p, g_hsl);
    cudaGetSymbolAddress((void**)&wifh, g_WiFh);
    cudaGetSymbolAddress((void**)&wifl, g_WiFl);
    cudaGetSymbolAddress((void**)&wofh, g_WoFh);
    cudaGetSymbolAddress((void**)&wofl, g_WoFl);

    // 0) init + splits + fragment scatters
    zero_state<<<(Bb * Hd + 255) / 256, 256>>>();
    split_xs<<<(int)(((size_t)Mrows * INd + 255) / 256), 256>>>(xs);
    prep_Bfrag<<<(NBLK * NKS * 2 * 32) / 256, 256>>>(Wh);
    prep_Wfrag<<<(WI_CG * WI_KS * 32) / 256, 256>>>(Wi, G4, WI_KS, wifh, wifl);
    prep_Wfrag<<<(WO_CG * WO_KS * 32) / 256, 256>>>(Wo, OUTd, WO_KS, wofh, wofl);

    // 1) xp = xs @ Wi + b   (HMMA)
    {
        dim3 grid(G4 / 64, Mrows / 128);
        gemm_mma<INd><<<grid, 256>>>(xsh_p, xsl_p, wifh, wifl, b, xp_p, G4);
    }

    // 2) recurrence: one persistent launch
    lstm_persist<<<NBLK, 256>>>();

    // 3) logits = hs @ Wo + bo   (HMMA)
    {
        dim3 grid(OUTd / 64, Mrows / 128);
        gemm_mma<Hd><<<grid, 256>>>(hsh_p, hsl_p, wofh, wofl, bo, out, OUTd);
    }
}

// round 8
// speedup vs baseline: 3.4776x; 1.3833x over previous
#include <cuda_runtime.h>
#include <cuda_bf16.h>
#include <math.h>
#include <stdint.h>

#define Bb   64
#define Tt   256
#define INd  512
#define Hd   1024
#define OUTd 512
#define G4   (4*Hd)        // 4096
#define Mrows (Bb*Tt)      // 16384

#define NBLK 128           // persistent blocks; each owns 8 hidden cols (x4 gates = N=32)
#define NJJ  8             // hidden cols per block
#define NKS  64            // k16 steps (K=1024)

// ---------------- scratch (device globals) ----------------
__device__ float g_xp[(size_t)Mrows * G4];          // [B*T, 4H]
__device__ __nv_bfloat16 g_xsh[(size_t)Mrows * INd];  // xs hi split
__device__ __nv_bfloat16 g_xsl[(size_t)Mrows * INd];  // xs lo split
__device__ __nv_bfloat16 g_hsh[(size_t)Mrows * Hd]; // hs hi split
__device__ __nv_bfloat16 g_hsl[(size_t)Mrows * Hd]; // hs lo split
__device__ __nv_bfloat16 g_hh[2][Bb * Hd];          // h hi (ping-pong)
__device__ __nv_bfloat16 g_hl[2][Bb * Hd];          // h lo
__device__ unsigned g_bar;                          // grid barrier counter
// Wh pre-scattered into HMMA B-fragment order (recurrence):
__device__ uint4 g_Bfh[(size_t)NBLK * NKS * 2 * 32];
__device__ uint4 g_Bfl[(size_t)NBLK * NKS * 2 * 32];
// Wi / Wo fragment arrays
#define WI_CG (G4/32)      // 128
#define WI_KS (INd/16)     // 32
#define WO_CG (OUTd/32)    // 16
#define WO_KS (Hd/16)      // 64
__device__ uint4 g_WiFh[(size_t)WI_CG * WI_KS * 32 * 2];
__device__ uint4 g_WiFl[(size_t)WI_CG * WI_KS * 32 * 2];
__device__ uint4 g_WoFh[(size_t)WO_CG * WO_KS * 32 * 2];
__device__ uint4 g_WoFl[(size_t)WO_CG * WO_KS * 32 * 2];

#define SW128(b) ((b) ^ (((b) >> 3) & 0x70))
#define BIDX(s, wx) ((((size_t)blk * NKS + (s)) * 2 + (wx)) * 32 + lane)

__device__ __forceinline__ uint32_t smem_u32(const void* p) {
    uint32_t a;
    asm("{ .reg .u64 t; cvta.to.shared.u64 t, %1; cvt.u32.u64 %0, t; }" : "=r"(a) : "l"(p));
    return a;
}
__device__ __forceinline__ void ldmatrix_x4(uint32_t* r, uint32_t addr) {
    asm volatile("ldmatrix.sync.aligned.m8n8.x4.shared.b16 {%0,%1,%2,%3}, [%4];"
                 : "=r"(r[0]), "=r"(r[1]), "=r"(r[2]), "=r"(r[3]) : "r"(addr));
}
__device__ __forceinline__ void mma_bf16(float* c, const uint32_t* a,
                                         uint32_t b0, uint32_t b1) {
    asm volatile(
        "mma.sync.aligned.m16n8k16.row.col.f32.bf16.bf16.f32 "
        "{%0,%1,%2,%3}, {%4,%5,%6,%7}, {%8,%9}, {%0,%1,%2,%3};"
        : "+f"(c[0]), "+f"(c[1]), "+f"(c[2]), "+f"(c[3])
        : "r"(a[0]), "r"(a[1]), "r"(a[2]), "r"(a[3]), "r"(b0), "r"(b1));
}
__device__ __forceinline__ uint4 ldg_cg(const void* p) {
    uint4 v;
    asm volatile("ld.global.cg.v4.u32 {%0,%1,%2,%3}, [%4];"
                 : "=r"(v.x), "=r"(v.y), "=r"(v.z), "=r"(v.w) : "l"(p));
    return v;
}
__device__ __forceinline__ uint32_t pack_bf16(float x, float y) {
    __nv_bfloat162 v = __floats2bfloat162_rn(x, y);
    return *(uint32_t*)&v;
}
#define CP_ASYNC16(sm, gp) \
    asm volatile("cp.async.cg.shared.global [%0], [%1], 16;" :: "r"(sm), "l"(gp))
#define CP_COMMIT() asm volatile("cp.async.commit_group;" ::: "memory")
#define CP_WAIT(n)  asm volatile("cp.async.wait_group %0;" :: "n"(n) : "memory")

// ---------------------------------------------------------------------------
__global__ void zero_state() {
    int i = blockIdx.x * blockDim.x + threadIdx.x;
    if (i == 0) g_bar = 0;
    if (i < Bb * Hd) {
        g_hh[0][i] = __float2bfloat16(0.f);
        g_hl[0][i] = __float2bfloat16(0.f);
    }
}

__global__ __launch_bounds__(256) void split_xs(const float* __restrict__ xs) {
    size_t i = (size_t)blockIdx.x * blockDim.x + threadIdx.x;
    if (i < (size_t)Mrows * INd) {
        float v = xs[i];
        __nv_bfloat16 hi = __float2bfloat16_rn(v);
        g_xsh[i] = hi;
        g_xsl[i] = __float2bfloat16_rn(v - __bfloat162float(hi));
    }
}

// ---------------------------------------------------------------------------
__global__ __launch_bounds__(256) void prep_Bfrag(const float* __restrict__ Wh) {
    int gid = blockIdx.x * blockDim.x + threadIdx.x;
    int lane = gid & 31;
    int wx   = (gid >> 5) & 1;
    int ks   = (gid >> 6) & 63;
    int blk  = gid >> 12;

    uint32_t outh[4], outl[4];
    #pragma unroll
    for (int t2 = 0; t2 < 2; t2++) {
        int loc = wx * 16 + t2 * 8 + (lane >> 2);
        int g = loc >> 3, jj = loc & 7;
        int col = g * Hd + blk * NJJ + jj;
        int kb = ks * 16 + (lane & 3) * 2;
        float w0 = Wh[(size_t)(kb + 0) * G4 + col];
        float w1 = Wh[(size_t)(kb + 1) * G4 + col];
        float w8 = Wh[(size_t)(kb + 8) * G4 + col];
        float w9 = Wh[(size_t)(kb + 9) * G4 + col];
        float h0 = __bfloat162float(__float2bfloat16_rn(w0));
        float h1 = __bfloat162float(__float2bfloat16_rn(w1));
        float h8 = __bfloat162float(__float2bfloat16_rn(w8));
        float h9 = __bfloat162float(__float2bfloat16_rn(w9));
        outh[t2*2+0] = pack_bf16(h0, h1);
        outh[t2*2+1] = pack_bf16(h8, h9);
        outl[t2*2+0] = pack_bf16(w0 - h0, w1 - h1);
        outl[t2*2+1] = pack_bf16(w8 - h8, w9 - h9);
    }
    g_Bfh[gid] = make_uint4(outh[0], outh[1], outh[2], outh[3]);
    g_Bfl[gid] = make_uint4(outl[0], outl[1], outl[2], outl[3]);
}

// ---------------------------------------------------------------------------
__global__ __launch_bounds__(256)
void prep_Wfrag(const float* __restrict__ W, int N, int KS,
                uint4* __restrict__ outh_arr, uint4* __restrict__ outl_arr) {
    int gid = blockIdx.x * blockDim.x + threadIdx.x;
    int lane = gid & 31;
    int s    = (gid >> 5) % KS;
    int cg   = (gid >> 5) / KS;

    const int k0 = s * 16 + (lane & 3) * 2;
    #pragma unroll
    for (int j = 0; j < 2; j++) {
        uint32_t oh[4], ol[4];
        #pragma unroll
        for (int tt = 0; tt < 2; tt++) {
            int col = cg * 32 + (j * 2 + tt) * 8 + (lane >> 2);
            float w0 = W[(size_t)(k0 + 0) * N + col];
            float w1 = W[(size_t)(k0 + 1) * N + col];
            float w8 = W[(size_t)(k0 + 8) * N + col];
            float w9 = W[(size_t)(k0 + 9) * N + col];
            float h0 = __bfloat162float(__float2bfloat16_rn(w0));
            float h1 = __bfloat162float(__float2bfloat16_rn(w1));
            float h8 = __bfloat162float(__float2bfloat16_rn(w8));
            float h9 = __bfloat162float(__float2bfloat16_rn(w9));
            oh[tt*2+0] = pack_bf16(h0, h1);
            oh[tt*2+1] = pack_bf16(h8, h9);
            ol[tt*2+0] = pack_bf16(w0 - h0, w1 - h1);
            ol[tt*2+1] = pack_bf16(w8 - h8, w9 - h9);
        }
        outh_arr[(size_t)gid * 2 + j] = make_uint4(oh[0], oh[1], oh[2], oh[3]);
        outl_arr[(size_t)gid * 2 + j] = make_uint4(ol[0], ol[1], ol[2], ol[3]);
    }
}

// ---------------------------------------------------------------------------
// bf16x3-split HMMA GEMM (unchanged from R6).
template<int K>
__global__ __launch_bounds__(256)
void gemm_mma(const __nv_bfloat16* __restrict__ Ah,
              const __nv_bfloat16* __restrict__ Al,
              const uint4* __restrict__ BfH, const uint4* __restrict__ BfL,
              const float* __restrict__ bias, float* __restrict__ C, int N) {
    constexpr int KS = K / 16;
    constexpr int NC = K / 64;
    __shared__ __align__(16) char smA[2][2][16384];

    const int tid  = threadIdx.x;
    const int lane = tid & 31;
    const int wid  = tid >> 5;
    const int wy   = wid & 3;
    const int wn   = wid >> 2;
    const int rowBase = blockIdx.y * 128;
    const int colBase = blockIdx.x * 64;
    const int cg = blockIdx.x * 2 + wn;

    const uint32_t uA[2][2] = {
        { smem_u32(smA[0][0]), smem_u32(smA[0][1]) },
        { smem_u32(smA[1][0]), smem_u32(smA[1][1]) } };

    int rowi[4], qi[4]; uint32_t offi[4];
    #pragma unroll
    for (int i = 0; i < 4; i++) {
        int idx = i * 256 + tid;
        rowi[i] = idx >> 3; qi[i] = idx & 7;
        offi[i] = SW128((uint32_t)(rowi[i] * 128 + qi[i] * 16));
    }
    #define ISSUE_A(buf, kb)                                                     \
        do {                                                                     \
            _Pragma("unroll")                                                    \
            for (int i = 0; i < 4; i++) {                                        \
                CP_ASYNC16(uA[buf][0] + offi[i],                                 \
                    &Ah[(size_t)(rowBase + rowi[i]) * K + (kb) + qi[i] * 8]);    \
                CP_ASYNC16(uA[buf][1] + offi[i],                                 \
                    &Al[(size_t)(rowBase + rowi[i]) * K + (kb) + qi[i] * 8]);    \
            }                                                                    \
            CP_COMMIT();                                                         \
        } while (0)

    float acc[2][4][4] = {};
    const int lr = lane & 15, lch = (lane >> 4) * 8;

    const size_t bbase = ((size_t)cg * KS) * 64 + lane * 2;
    uint4 BH[2][2], BL[2][2];
    #pragma unroll
    for (int s = 0; s < 2; s++) {
        BH[s][0] = BfH[bbase + s * 64 + 0];
        BH[s][1] = BfH[bbase + s * 64 + 1];
        BL[s][0] = BfL[bbase + s * 64 + 0];
        BL[s][1] = BfL[bbase + s * 64 + 1];
    }

    ISSUE_A(0, 0);

    for (int kc = 0; kc < NC; kc++) {
        if (kc + 1 < NC) { ISSUE_A((kc + 1) & 1, (kc + 1) * 64); CP_WAIT(1); }
        else             { CP_WAIT(0); }
        __syncthreads();

        const uint32_t uh = uA[kc & 1][0], ul = uA[kc & 1][1];
        #pragma unroll
        for (int ks = 0; ks < 4; ks++) {
            const int s = kc * 4 + ks;
            uint4 bh0 = BH[ks & 1][0], bh1 = BH[ks & 1][1];
            uint4 bl0 = BL[ks & 1][0], bl1 = BL[ks & 1][1];
            if (s + 2 < KS) {
                BH[ks & 1][0] = BfH[bbase + (size_t)(s + 2) * 64 + 0];
                BH[ks & 1][1] = BfH[bbase + (size_t)(s + 2) * 64 + 1];
                BL[ks & 1][0] = BfL[bbase + (size_t)(s + 2) * 64 + 0];
                BL[ks & 1][1] = BfL[bbase + (size_t)(s + 2) * 64 + 1];
            }
            #pragma unroll
            for (int mt = 0; mt < 2; mt++) {
                const int lrow = wy * 32 + mt * 16 + lr;
                uint32_t offA = SW128((uint32_t)(lrow * 128 + (ks * 16 + lch) * 2));
                uint32_t ah[4], al[4];
                ldmatrix_x4(ah, uh + offA);
                ldmatrix_x4(al, ul + offA);

                mma_bf16(acc[mt][0], ah, bh0.x, bh0.y);
                mma_bf16(acc[mt][1], ah, bh0.z, bh0.w);
                mma_bf16(acc[mt][2], ah, bh1.x, bh1.y);
                mma_bf16(acc[mt][3], ah, bh1.z, bh1.w);
                mma_bf16(acc[mt][0], al, bh0.x, bh0.y);
                mma_bf16(acc[mt][1], al, bh0.z, bh0.w);
                mma_bf16(acc[mt][2], al, bh1.x, bh1.y);
                mma_bf16(acc[mt][3], al, bh1.z, bh1.w);
                mma_bf16(acc[mt][0], ah, bl0.x, bl0.y);
                mma_bf16(acc[mt][1], ah, bl0.z, bl0.w);
                mma_bf16(acc[mt][2], ah, bl1.x, bl1.y);
                mma_bf16(acc[mt][3], ah, bl1.z, bl1.w);
            }
        }
        __syncthreads();
    }

    const int r = lane >> 2, cc = (lane & 3) * 2;
    #pragma unroll
    for (int mt = 0; mt < 2; mt++) {
        const int m = rowBase + wy * 32 + mt * 16 + r;
        #pragma unroll
        for (int nt = 0; nt < 4; nt++) {
            const int n = colBase + wn * 32 + nt * 8 + cc;
            float b0 = bias[n], b1 = bias[n + 1];
            *(float2*)&C[(size_t)m * N + n] =
                make_float2(acc[mt][nt][0] + b0, acc[mt][nt][1] + b1);
            *(float2*)&C[(size_t)(m + 8) * N + n] =
                make_float2(acc[mt][nt][2] + b0, acc[mt][nt][3] + b1);
        }
    }
    #undef ISSUE_A
}

// ---------------------------------------------------------------------------
// Persistent HMMA LSTM v2: 8 warps = 4 M-tiles (wy) x 2 K-halves (wk).
// Each warp: 16 rows x 32 cols x K/2, 4 accumulator chains. K=128 chunks
// (2 panels of 64), wk interleaved within each chunk. smem reduction over wk.
// Barrier: atomic arrive + volatile-load poll. xp prefetched pre-barrier.
__global__ __launch_bounds__(256)
void lstm_persist() {
    extern __shared__ char dyn_sm[];
    // [buf][split][panel][8192]; then Ds[64][32] floats
    char (*smA)[2][2][8192] = (char (*)[2][2][8192])dyn_sm;
    float (*Ds)[32] = (float (*)[32])(dyn_sm + 65536);

    const int tid = threadIdx.x;
    const int lane = tid & 31;
    const int wid = tid >> 5;
    const int wy = wid & 3;          // M tile
    const int wk = wid >> 2;         // K half
    const int blk = blockIdx.x;
    const int jbase = blk * NJJ;

    const int lrow = wy * 16 + (lane & 15);
    const int lch  = (lane >> 4) * 8;

    // A staging: 4 uint4 per thread per split per K=128 chunk
    int pan[4], prow[4], pq[4]; uint32_t poff[4];
    #pragma unroll
    for (int i = 0; i < 4; i++) {
        int idx = i * 256 + tid;          // 0..1023
        pan[i]  = idx >> 9;               // panel 0/1
        int i2  = idx & 511;
        prow[i] = i2 >> 3;                // row 0..63
        pq[i]   = i2 & 7;                 // 16B group
        poff[i] = SW128((uint32_t)(prow[i] * 128 + pq[i] * 16));
    }

    uint32_t uP[2][2][2];  // [buf][split][panel]
    #pragma unroll
    for (int bu = 0; bu < 2; bu++)
        #pragma unroll
        for (int sp = 0; sp < 2; sp++)
            #pragma unroll
            for (int pp = 0; pp < 2; pp++)
                uP[bu][sp][pp] = smem_u32(smA[bu][sp][pp]);

    const int ob0 = (tid * 2) >> 3,     oj0 = (tid * 2) & 7;
    const int ob1 = (tid * 2 + 1) >> 3, oj1 = (tid * 2 + 1) & 7;
    float c_r[2] = {0.f, 0.f};

    // prefetch xp for step 0
    float xg[2][4];
    #pragma unroll
    for (int g = 0; g < 4; g++) {
        xg[0][g] = g_xp[((size_t)ob0 * Tt + 0) * G4 + g * Hd + jbase + oj0];
        xg[1][g] = g_xp[((size_t)ob1 * Tt + 0) * G4 + g * Hd + jbase + oj1];
    }

    for (int t = 0; t < Tt; t++) {
        const __nv_bfloat16* hh = g_hh[t & 1];
        const __nv_bfloat16* hl = g_hl[t & 1];

        // chunk 0 A loads
        uint4 ra[2][4];
        #pragma unroll
        for (int i = 0; i < 4; i++) {
            ra[0][i] = ldg_cg(&hh[prow[i] * Hd + pan[i] * 64 + pq[i] * 8]);
            ra[1][i] = ldg_cg(&hl[prow[i] * Hd + pan[i] * 64 + pq[i] * 8]);
        }
        // B ring: iteration u = c*4+ks', s(u) = (u>>2)*8 + wk*4 + (u&3)
        uint4 BH0[2], BH1[2], BL0[2], BL1[2];
        #pragma unroll
        for (int u = 0; u < 2; u++) {
            const int s = (u >> 2) * 8 + wk * 4 + (u & 3);
            BH0[u] = g_Bfh[BIDX(s, 0)]; BH1[u] = g_Bfh[BIDX(s, 1)];
            BL0[u] = g_Bfl[BIDX(s, 0)]; BL1[u] = g_Bfl[BIDX(s, 1)];
        }
        #pragma unroll
        for (int i = 0; i < 4; i++) {
            *(uint4*)(smA[0][0][pan[i]] + poff[i]) = ra[0][i];
            *(uint4*)(smA[0][1][pan[i]] + poff[i]) = ra[1][i];
        }
        __syncthreads();

        float acc[4][4] = {};   // [n-tile][frag]

        for (int c = 0; c < 8; c++) {
            const int cn = c + 1;
            if (cn < 8) {
                #pragma unroll
                for (int i = 0; i < 4; i++) {
                    ra[0][i] = ldg_cg(&hh[prow[i] * Hd + cn * 128 + pan[i] * 64 + pq[i] * 8]);
                    ra[1][i] = ldg_cg(&hl[prow[i] * Hd + cn * 128 + pan[i] * 64 + pq[i] * 8]);
                }
            }
            // warp wk consumes panel wk of this chunk
            const uint32_t uh = uP[c & 1][0][wk], ul = uP[c & 1][1][wk];

            #pragma unroll
            for (int ks = 0; ks < 4; ks++) {
                const int u = c * 4 + ks;
                uint4 bh0 = BH0[u & 1], bh1 = BH1[u & 1];
                uint4 bl0 = BL0[u & 1], bl1 = BL1[u & 1];
                if (u + 2 < 32) {
                    const int s2 = ((u + 2) >> 2) * 8 + wk * 4 + ((u + 2) & 3);
                    BH0[u & 1] = g_Bfh[BIDX(s2, 0)];
                    BH1[u & 1] = g_Bfh[BIDX(s2, 1)];
                    BL0[u & 1] = g_Bfl[BIDX(s2, 0)];
                    BL1[u & 1] = g_Bfl[BIDX(s2, 1)];
                }
                uint32_t offA = SW128((uint32_t)(lrow * 128 + (ks * 16 + lch) * 2));
                uint32_t ah[4], al[4];
                ldmatrix_x4(ah, uh + offA);
                ldmatrix_x4(al, ul + offA);

                mma_bf16(acc[0], ah, bh0.x, bh0.y);
                mma_bf16(acc[1], ah, bh0.z, bh0.w);
                mma_bf16(acc[2], ah, bh1.x, bh1.y);
                mma_bf16(acc[3], ah, bh1.z, bh1.w);
                mma_bf16(acc[0], al, bh0.x, bh0.y);
                mma_bf16(acc[1], al, bh0.z, bh0.w);
                mma_bf16(acc[2], al, bh1.x, bh1.y);
                mma_bf16(acc[3], al, bh1.z, bh1.w);
                mma_bf16(acc[0], ah, bl0.x, bl0.y);
                mma_bf16(acc[1], ah, bl0.z, bl0.w);
                mma_bf16(acc[2], ah, bl1.x, bl1.y);
                mma_bf16(acc[3], ah, bl1.z, bl1.w);
            }

            if (cn < 8) {
                #pragma unroll
                for (int i = 0; i < 4; i++) {
                    *(uint4*)(smA[cn & 1][0][pan[i]] + poff[i]) = ra[0][i];
                    *(uint4*)(smA[cn & 1][1][pan[i]] + poff[i]) = ra[1][i];
                }
            }
            __syncthreads();
        }

        // reduce wk halves through Ds
        const int r = lane >> 2, cc = (lane & 3) * 2;
        const int m0 = wy * 16;
        if (wk == 0) {
            #pragma unroll
            for (int nt = 0; nt < 4; nt++) {
                Ds[m0 + r    ][nt * 8 + cc    ] = acc[nt][0];
                Ds[m0 + r    ][nt * 8 + cc + 1] = acc[nt][1];
                Ds[m0 + r + 8][nt * 8 + cc    ] = acc[nt][2];
                Ds[m0 + r + 8][nt * 8 + cc + 1] = acc[nt][3];
            }
        }
        __syncthreads();
        if (wk == 1) {
            #pragma unroll
            for (int nt = 0; nt < 4; nt++) {
                Ds[m0 + r    ][nt * 8 + cc    ] += acc[nt][0];
                Ds[m0 + r    ][nt * 8 + cc + 1] += acc[nt][1];
                Ds[m0 + r + 8][nt * 8 + cc    ] += acc[nt][2];
                Ds[m0 + r + 8][nt * 8 + cc + 1] += acc[nt][3];
            }
        }
        __syncthreads();

        // fused nonlinearity (xg prefetched last step)
        #pragma unroll
        for (int u = 0; u < 2; u++) {
            const int b  = u ? ob1 : ob0;
            const int jj = u ? oj1 : oj0;
            float gi = Ds[b][0*8 + jj] + xg[u][0];
            float gf = Ds[b][1*8 + jj] + xg[u][1];
            float gg = Ds[b][2*8 + jj] + xg[u][2];
            float go = Ds[b][3*8 + jj] + xg[u][3];

            float si = 1.f / (1.f + expf(-gi));
            float sf = 1.f / (1.f + expf(-gf));
            float so = 1.f / (1.f + expf(-go));
            float tg = tanhf(gg);

            float cN = sf * c_r[u] + si * tg;
            c_r[u] = cN;
            float hN = so * tanhf(cN);

            const int ci = b * Hd + jbase + jj;
            __nv_bfloat16 hi = __float2bfloat16_rn(hN);
            __nv_bfloat16 lo = __float2bfloat16_rn(hN - __bfloat162float(hi));
            g_hh[(t + 1) & 1][ci] = hi;
            g_hl[(t + 1) & 1][ci] = lo;
            const size_t hsi = ((size_t)b * Tt + t) * Hd + jbase + jj;
            g_hsh[hsi] = hi;
            g_hsl[hsi] = lo;
        }

        // prefetch xp for t+1 (independent of barrier)
        if (t + 1 < Tt) {
            #pragma unroll
            for (int g = 0; g < 4; g++) {
                xg[0][g] = g_xp[((size_t)ob0 * Tt + t + 1) * G4 + g * Hd + jbase + oj0];
                xg[1][g] = g_xp[((size_t)ob1 * Tt + t + 1) * G4 + g * Hd + jbase + oj1];
            }
        }

        // grid barrier: atomic arrive, volatile-load poll
        __syncthreads();
        if (tid == 0) {
            __threadfence();
            atomicAdd(&g_bar, 1u);
            const unsigned tgt = (unsigned)(t + 1) * (unsigned)NBLK;
            while (*(volatile unsigned*)&g_bar < tgt) { }
            __threadfence();
        }
        __syncthreads();
    }
}

// ---------------------------------------------------------------------------
extern "C" void kernel_launch(void* const* d_in, const int* in_sizes, int n_in,
                              void* d_out, int out_size) {
    const float* xs = (const float*)d_in[0];
    const float* Wi = (const float*)d_in[1];
    const float* Wh = (const float*)d_in[2];
    const float* b  = (const float*)d_in[3];
    const float* Wo = (const float*)d_in[4];
    const float* bo = (const float*)d_in[5];
    float* out = (float*)d_out;

    float* xp_p = nullptr;
    __nv_bfloat16 *xsh_p = nullptr, *xsl_p = nullptr, *hsh_p = nullptr, *hsl_p = nullptr;
    uint4 *wifh = nullptr, *wifl = nullptr, *wofh = nullptr, *wofl = nullptr;
    cudaGetSymbolAddress((void**)&xp_p, g_xp);
    cudaGetSymbolAddress((void**)&xsh_p, g_xsh);
    cudaGetSymbolAddress((void**)&xsl_p, g_xsl);
    cudaGetSymbolAddress((void**)&hsh_p, g_hsh);
    cudaGetSymbolAddress((void**)&hsl_p, g_hsl);
    cudaGetSymbolAddress((void**)&wifh, g_WiFh);
    cudaGetSymbolAddress((void**)&wifl, g_WiFl);
    cudaGetSymbolAddress((void**)&wofh, g_WoFh);
    cudaGetSymbolAddress((void**)&wofl, g_WoFl);

    const int lp_smem = 65536 + 64 * 32 * 4;   // panels + Ds = 73728
    cudaFuncSetAttribute(lstm_persist,
                         cudaFuncAttributeMaxDynamicSharedMemorySize, lp_smem);

    // 0) init + splits + fragment scatters
    zero_state<<<(Bb * Hd + 255) / 256, 256>>>();
    split_xs<<<(int)(((size_t)Mrows * INd + 255) / 256), 256>>>(xs);
    prep_Bfrag<<<(NBLK * NKS * 2 * 32) / 256, 256>>>(Wh);
    prep_Wfrag<<<(WI_CG * WI_KS * 32) / 256, 256>>>(Wi, G4, WI_KS, wifh, wifl);
    prep_Wfrag<<<(WO_CG * WO_KS * 32) / 256, 256>>>(Wo, OUTd, WO_KS, wofh, wofl);

    // 1) xp = xs @ Wi + b   (HMMA)
    {
        dim3 grid(G4 / 64, Mrows / 128);
        gemm_mma<INd><<<grid, 256>>>(xsh_p, xsl_p, wifh, wifl, b, xp_p, G4);
    }

    // 2) recurrence: one persistent launch
    lstm_persist<<<NBLK, 256, lp_smem>>>();

    // 3) logits = hs @ Wo + bo   (HMMA)
    {
        dim3 grid(OUTd / 64, Mrows / 128);
        gemm_mma<Hd><<<grid, 256>>>(hsh_p, hsl_p, wofh, wofl, bo, out, OUTd);
    }
}